// round 1
// baseline (speedup 1.0000x reference)
#include <cuda_runtime.h>
#include <math.h>

#define D_MODEL 256
#define D_FF    1024
#define N_HEADS 4
#define D_K     64
#define B_      4
#define T_      2048
#define BT      8192
#define RMS_EPS 1e-5f

// -------------------- scratch (no allocs allowed) --------------------
__device__ float g_h[BT * D_MODEL];     // rmsnorm out, reused as attn_out
__device__ float g_q[BT * D_MODEL];
__device__ float g_k[BT * D_MODEL];
__device__ float g_v[BT * D_MODEL];
__device__ float g_x1[BT * D_MODEL];
__device__ float g_hf[BT * D_MODEL];
__device__ float g_gate[BT * D_FF];
__device__ float g_up[BT * D_FF];

// -------------------- rmsnorm: 1 block per row --------------------
__global__ void rmsnorm_kernel(const float* __restrict__ x,
                               const float* __restrict__ w,
                               float* __restrict__ out) {
    const int row = blockIdx.x;
    const int tid = threadIdx.x;
    const float v = x[(size_t)row * D_MODEL + tid];
    float ss = v * v;
#pragma unroll
    for (int m = 16; m; m >>= 1) ss += __shfl_xor_sync(0xffffffffu, ss, m);
    __shared__ float ws[8];
    __shared__ float s_tot;
    if ((tid & 31) == 0) ws[tid >> 5] = ss;
    __syncthreads();
    if (tid < 8) {
        float t = ws[tid];
        t += __shfl_xor_sync(0xffu, t, 4);
        t += __shfl_xor_sync(0xffu, t, 2);
        t += __shfl_xor_sync(0xffu, t, 1);
        if (tid == 0) s_tot = t;
    }
    __syncthreads();
    const float r = rsqrtf(s_tot * (1.0f / D_MODEL) + RMS_EPS);
    out[(size_t)row * D_MODEL + tid] = v * r * w[tid];
}

// -------------------- 128x128x8 SGEMM core: C = A * W^T (+res) --------------------
// A: [M,K] row-major, W: [N,K] row-major, C/res: [M,N] row-major.
__device__ __forceinline__ void gemm128_core(const float* __restrict__ A,
                                             const float* __restrict__ W,
                                             const float* __restrict__ res,
                                             float* __restrict__ C,
                                             int N, int K,
                                             float* As, float* Bs) {
    const int tid = threadIdx.x;
    const int tx = tid & 15, ty = tid >> 4;
    const int bm = blockIdx.x * 128, bn = blockIdx.y * 128;

    float acc[8][8];
#pragma unroll
    for (int i = 0; i < 8; i++)
#pragma unroll
        for (int j = 0; j < 8; j++) acc[i][j] = 0.f;

    const int lm = tid >> 1;          // 0..127
    const int lk = (tid & 1) << 2;    // 0 or 4
    const float* Ag = A + (size_t)(bm + lm) * K + lk;
    const float* Wg = W + (size_t)(bn + lm) * K + lk;

    for (int k0 = 0; k0 < K; k0 += 8) {
        float4 av = *(const float4*)(Ag + k0);
        float4 wv = *(const float4*)(Wg + k0);
        As[(lk + 0) * 132 + lm] = av.x;
        As[(lk + 1) * 132 + lm] = av.y;
        As[(lk + 2) * 132 + lm] = av.z;
        As[(lk + 3) * 132 + lm] = av.w;
        Bs[(lk + 0) * 132 + lm] = wv.x;
        Bs[(lk + 1) * 132 + lm] = wv.y;
        Bs[(lk + 2) * 132 + lm] = wv.z;
        Bs[(lk + 3) * 132 + lm] = wv.w;
        __syncthreads();
#pragma unroll
        for (int kk = 0; kk < 8; kk++) {
            float4 a0 = *(const float4*)&As[kk * 132 + ty * 4];
            float4 a1 = *(const float4*)&As[kk * 132 + 64 + ty * 4];
            float4 b0 = *(const float4*)&Bs[kk * 132 + tx * 4];
            float4 b1 = *(const float4*)&Bs[kk * 132 + 64 + tx * 4];
            float af[8] = {a0.x, a0.y, a0.z, a0.w, a1.x, a1.y, a1.z, a1.w};
            float bf[8] = {b0.x, b0.y, b0.z, b0.w, b1.x, b1.y, b1.z, b1.w};
#pragma unroll
            for (int i = 0; i < 8; i++)
#pragma unroll
                for (int j = 0; j < 8; j++) acc[i][j] += af[i] * bf[j];
        }
        __syncthreads();
    }

#pragma unroll
    for (int ri = 0; ri < 2; ri++)
#pragma unroll
        for (int ii = 0; ii < 4; ii++) {
            const int row = bm + ri * 64 + ty * 4 + ii;
#pragma unroll
            for (int ci = 0; ci < 2; ci++) {
                const int col = bn + ci * 64 + tx * 4;
                float4 o;
                o.x = acc[ri * 4 + ii][ci * 4 + 0];
                o.y = acc[ri * 4 + ii][ci * 4 + 1];
                o.z = acc[ri * 4 + ii][ci * 4 + 2];
                o.w = acc[ri * 4 + ii][ci * 4 + 3];
                if (res) {
                    float4 rr = *(const float4*)&res[(size_t)row * N + col];
                    o.x += rr.x; o.y += rr.y; o.z += rr.z; o.w += rr.w;
                }
                *(float4*)&C[(size_t)row * N + col] = o;
            }
        }
}

__global__ void __launch_bounds__(256) gemm_qkv_kernel(
    const float* __restrict__ h,
    const float* __restrict__ wq, const float* __restrict__ wk, const float* __restrict__ wv,
    float* __restrict__ q, float* __restrict__ k, float* __restrict__ v) {
    __shared__ float As[8 * 132];
    __shared__ float Bs[8 * 132];
    const float* W;
    float* C;
    if (blockIdx.z == 0) { W = wq; C = q; }
    else if (blockIdx.z == 1) { W = wk; C = k; }
    else { W = wv; C = v; }
    gemm128_core(h, W, nullptr, C, D_MODEL, D_MODEL, As, Bs);
}

__global__ void __launch_bounds__(256) gemm_res_kernel(
    const float* __restrict__ A, const float* __restrict__ W,
    const float* __restrict__ res, float* __restrict__ C, int N, int K) {
    __shared__ float As[8 * 132];
    __shared__ float Bs[8 * 132];
    gemm128_core(A, W, res, C, N, K, As, Bs);
}

__global__ void __launch_bounds__(256) gemm_gateup_kernel(
    const float* __restrict__ hf,
    const float* __restrict__ wg, const float* __restrict__ wu,
    float* __restrict__ gate, float* __restrict__ up) {
    __shared__ float As[8 * 132];
    __shared__ float Bs[8 * 132];
    const float* W = (blockIdx.z == 0) ? wg : wu;
    float* C = (blockIdx.z == 0) ? gate : up;
    gemm128_core(hf, W, nullptr, C, D_FF, D_MODEL, As, Bs);
}

// -------------------- flash attention (fp32, 64x64 tiles, online softmax) ------
// Layout of Q/K/V: [B*T, H*Dk], head h at cols [h*64, h*64+64).
__global__ void __launch_bounds__(256) flash_kernel(const float* __restrict__ Q,
                                                    const float* __restrict__ K,
                                                    const float* __restrict__ V,
                                                    float* __restrict__ O) {
    extern __shared__ float sm[];
    float* Qt = sm;              // [64][68], Qt[d][m]
    float* KP = sm + 64 * 68;    // Kt[d][n] during S, Ps[r][j] during PV
    float* Vs = sm + 2 * 64 * 68; // Vs[j][oc]

    const int qt = blockIdx.x, h = blockIdx.y, b = blockIdx.z;
    const int tid = threadIdx.x, tx = tid & 15, ty = tid >> 4;
    const int q0 = qt * 64;
    const size_t base = ((size_t)b * T_) * D_MODEL + h * D_K;

    // load Q tile transposed
#pragma unroll
    for (int it = 0; it < 4; it++) {
        int idx = tid + it * 256;
        int m = idx >> 4, d4 = (idx & 15) << 2;
        float4 qv = *(const float4*)&Q[base + (size_t)(q0 + m) * D_MODEL + d4];
        Qt[(d4 + 0) * 68 + m] = qv.x;
        Qt[(d4 + 1) * 68 + m] = qv.y;
        Qt[(d4 + 2) * 68 + m] = qv.z;
        Qt[(d4 + 3) * 68 + m] = qv.w;
    }

    float m_i[4], l_i[4], acc[4][4];
#pragma unroll
    for (int i = 0; i < 4; i++) {
        m_i[i] = -1e30f;
        l_i[i] = 0.f;
#pragma unroll
        for (int j = 0; j < 4; j++) acc[i][j] = 0.f;
    }

    for (int kt = 0; kt <= qt; kt++) {
        const int k0 = kt * 64;
        __syncthreads();  // prev PV reads of KP/Vs done
#pragma unroll
        for (int it = 0; it < 4; it++) {
            int idx = tid + it * 256;
            int n = idx >> 4, d4 = (idx & 15) << 2;
            float4 kv = *(const float4*)&K[base + (size_t)(k0 + n) * D_MODEL + d4];
            KP[(d4 + 0) * 68 + n] = kv.x;
            KP[(d4 + 1) * 68 + n] = kv.y;
            KP[(d4 + 2) * 68 + n] = kv.z;
            KP[(d4 + 3) * 68 + n] = kv.w;
            float4 vv = *(const float4*)&V[base + (size_t)(k0 + n) * D_MODEL + d4];
            *(float4*)&Vs[n * 68 + d4] = vv;
        }
        __syncthreads();

        // S = Q K^T
        float s[4][4];
#pragma unroll
        for (int i = 0; i < 4; i++)
#pragma unroll
            for (int j = 0; j < 4; j++) s[i][j] = 0.f;
#pragma unroll 8
        for (int d = 0; d < 64; d++) {
            float4 a = *(const float4*)&Qt[d * 68 + ty * 4];
            float4 bb = *(const float4*)&KP[d * 68 + tx * 4];
            float af[4] = {a.x, a.y, a.z, a.w};
            float bf[4] = {bb.x, bb.y, bb.z, bb.w};
#pragma unroll
            for (int i = 0; i < 4; i++)
#pragma unroll
                for (int j = 0; j < 4; j++) s[i][j] += af[i] * bf[j];
        }

        const float sc = 0.125f;  // 1/sqrt(64)
        float p[4][4], alpha[4];
#pragma unroll
        for (int i = 0; i < 4; i++) {
            const int grow = q0 + ty * 4 + i;
#pragma unroll
            for (int j = 0; j < 4; j++) {
                s[i][j] *= sc;
                if (kt == qt && (k0 + tx * 4 + j) > grow) s[i][j] = -1e30f;
            }
            float mx = fmaxf(fmaxf(s[i][0], s[i][1]), fmaxf(s[i][2], s[i][3]));
            mx = fmaxf(mx, __shfl_xor_sync(0xffffffffu, mx, 1));
            mx = fmaxf(mx, __shfl_xor_sync(0xffffffffu, mx, 2));
            mx = fmaxf(mx, __shfl_xor_sync(0xffffffffu, mx, 4));
            mx = fmaxf(mx, __shfl_xor_sync(0xffffffffu, mx, 8));
            const float nm = fmaxf(m_i[i], mx);
            alpha[i] = __expf(m_i[i] - nm);
            m_i[i] = nm;
            float ps = 0.f;
#pragma unroll
            for (int j = 0; j < 4; j++) {
                p[i][j] = __expf(s[i][j] - nm);
                ps += p[i][j];
            }
            ps += __shfl_xor_sync(0xffffffffu, ps, 1);
            ps += __shfl_xor_sync(0xffffffffu, ps, 2);
            ps += __shfl_xor_sync(0xffffffffu, ps, 4);
            ps += __shfl_xor_sync(0xffffffffu, ps, 8);
            l_i[i] = l_i[i] * alpha[i] + ps;
#pragma unroll
            for (int j = 0; j < 4; j++) acc[i][j] *= alpha[i];
        }

        __syncthreads();  // all warps done reading KP as Kt
#pragma unroll
        for (int i = 0; i < 4; i++)
#pragma unroll
            for (int j = 0; j < 4; j++)
                KP[(ty * 4 + i) * 68 + tx * 4 + j] = p[i][j];
        __syncthreads();

        // acc += P * V
#pragma unroll 4
        for (int j = 0; j < 64; j++) {
            float4 vv = *(const float4*)&Vs[j * 68 + tx * 4];
            float p0 = KP[(ty * 4 + 0) * 68 + j];
            float p1 = KP[(ty * 4 + 1) * 68 + j];
            float p2 = KP[(ty * 4 + 2) * 68 + j];
            float p3 = KP[(ty * 4 + 3) * 68 + j];
            acc[0][0] += p0 * vv.x; acc[0][1] += p0 * vv.y; acc[0][2] += p0 * vv.z; acc[0][3] += p0 * vv.w;
            acc[1][0] += p1 * vv.x; acc[1][1] += p1 * vv.y; acc[1][2] += p1 * vv.z; acc[1][3] += p1 * vv.w;
            acc[2][0] += p2 * vv.x; acc[2][1] += p2 * vv.y; acc[2][2] += p2 * vv.z; acc[2][3] += p2 * vv.w;
            acc[3][0] += p3 * vv.x; acc[3][1] += p3 * vv.y; acc[3][2] += p3 * vv.z; acc[3][3] += p3 * vv.w;
        }
    }

#pragma unroll
    for (int i = 0; i < 4; i++) {
        const float inv = 1.0f / l_i[i];
        float4 o;
        o.x = acc[i][0] * inv;
        o.y = acc[i][1] * inv;
        o.z = acc[i][2] * inv;
        o.w = acc[i][3] * inv;
        *(float4*)&O[base + (size_t)(q0 + ty * 4 + i) * D_MODEL + tx * 4] = o;
    }
}

// -------------------- silu(gate) * up --------------------
__global__ void silu_mul_kernel(const float* __restrict__ g, const float* __restrict__ u,
                                float* __restrict__ out, int n) {
    int i = blockIdx.x * blockDim.x + threadIdx.x;
    if (i < n) {
        float x = g[i];
        out[i] = (x / (1.0f + __expf(-x))) * u[i];
    }
}

// -------------------- launch --------------------
extern "C" void kernel_launch(void* const* d_in, const int* in_sizes, int n_in,
                              void* d_out, int out_size) {
    const float* x          = (const float*)d_in[0];
    // d_in[1] = causal_mask (bool) — causality is handled analytically, unused
    const float* rms_attn_w = (const float*)d_in[2];
    const float* wq         = (const float*)d_in[3];
    const float* wk         = (const float*)d_in[4];
    const float* wv         = (const float*)d_in[5];
    const float* wo         = (const float*)d_in[6];
    const float* rms_ffn_w  = (const float*)d_in[7];
    const float* wg         = (const float*)d_in[8];
    const float* wu         = (const float*)d_in[9];
    const float* wd         = (const float*)d_in[10];
    float* out = (float*)d_out;

    float *h, *q, *k, *v, *x1, *hf, *gate, *up;
    cudaGetSymbolAddress((void**)&h, g_h);
    cudaGetSymbolAddress((void**)&q, g_q);
    cudaGetSymbolAddress((void**)&k, g_k);
    cudaGetSymbolAddress((void**)&v, g_v);
    cudaGetSymbolAddress((void**)&x1, g_x1);
    cudaGetSymbolAddress((void**)&hf, g_hf);
    cudaGetSymbolAddress((void**)&gate, g_gate);
    cudaGetSymbolAddress((void**)&up, g_up);

    const int FLASH_SMEM = 3 * 64 * 68 * sizeof(float);  // 52224 B
    cudaFuncSetAttribute(flash_kernel, cudaFuncAttributeMaxDynamicSharedMemorySize, FLASH_SMEM);

    // 1. h = rmsnorm(x)
    rmsnorm_kernel<<<BT, 256>>>(x, rms_attn_w, h);
    // 2. q,k,v = h @ {wq,wk,wv}^T
    gemm_qkv_kernel<<<dim3(BT / 128, D_MODEL / 128, 3), 256>>>(h, wq, wk, wv, q, k, v);
    // 3. attn_out (into h, which is dead now)
    flash_kernel<<<dim3(T_ / 64, N_HEADS, B_), 256, FLASH_SMEM>>>(q, k, v, h);
    // 4. x1 = x + attn_out @ wo^T
    gemm_res_kernel<<<dim3(BT / 128, D_MODEL / 128), 256>>>(h, wo, x, x1, D_MODEL, D_MODEL);
    // 5. hf = rmsnorm(x1)
    rmsnorm_kernel<<<BT, 256>>>(x1, rms_ffn_w, hf);
    // 6. gate, up
    gemm_gateup_kernel<<<dim3(BT / 128, D_FF / 128, 2), 256>>>(hf, wg, wu, gate, up);
    // 7. gate = silu(gate) * up
    silu_mul_kernel<<<(BT * D_FF) / 256, 256>>>(gate, up, gate, BT * D_FF);
    // 8. out = x1 + gate @ wd^T
    gemm_res_kernel<<<dim3(BT / 128, D_MODEL / 128), 256>>>(gate, wd, x1, out, D_MODEL, D_FF);
}

// round 2
// speedup vs baseline: 2.5695x; 2.5695x over previous
#include <cuda_runtime.h>
#include <stdint.h>
#include <math.h>

#define D_MODEL 256
#define D_FF    1024
#define T_      2048
#define B_      4
#define BT      8192
#define RMS_EPS 1e-5f

// -------------------- scratch (no allocs allowed) --------------------
__device__ float g_h[BT * D_MODEL];     // rmsnorm out, reused as attn_out
__device__ float g_q[BT * D_MODEL];
__device__ float g_k[BT * D_MODEL];
__device__ float g_v[BT * D_MODEL];
__device__ float g_x1[BT * D_MODEL];
__device__ float g_hf[BT * D_MODEL];
__device__ float g_gate[BT * D_FF];
__device__ float g_up[BT * D_FF];

// -------------------- tf32 helpers --------------------
__device__ __forceinline__ uint32_t f2tf(float x) {
    uint32_t u;
    asm("cvt.rna.tf32.f32 %0, %1;" : "=r"(u) : "f"(x));
    return u;
}

__device__ __forceinline__ void mma8(float* d,
                                     uint32_t a0, uint32_t a1, uint32_t a2, uint32_t a3,
                                     uint32_t b0, uint32_t b1) {
    asm volatile(
        "mma.sync.aligned.m16n8k8.row.col.f32.tf32.tf32.f32 "
        "{%0,%1,%2,%3},{%4,%5,%6,%7},{%8,%9},{%0,%1,%2,%3};"
        : "+f"(d[0]), "+f"(d[1]), "+f"(d[2]), "+f"(d[3])
        : "r"(a0), "r"(a1), "r"(a2), "r"(a3), "r"(b0), "r"(b1));
}

// -------------------- rmsnorm: 1 block per row --------------------
__global__ void rmsnorm_kernel(const float* __restrict__ x,
                               const float* __restrict__ w,
                               float* __restrict__ out) {
    const int row = blockIdx.x;
    const int tid = threadIdx.x;
    const float v = x[(size_t)row * D_MODEL + tid];
    float ss = v * v;
#pragma unroll
    for (int m = 16; m; m >>= 1) ss += __shfl_xor_sync(0xffffffffu, ss, m);
    __shared__ float ws[8];
    __shared__ float s_tot;
    if ((tid & 31) == 0) ws[tid >> 5] = ss;
    __syncthreads();
    if (tid < 8) {
        float t = ws[tid];
        t += __shfl_xor_sync(0xffu, t, 4);
        t += __shfl_xor_sync(0xffu, t, 2);
        t += __shfl_xor_sync(0xffu, t, 1);
        if (tid == 0) s_tot = t;
    }
    __syncthreads();
    const float r = rsqrtf(s_tot * (1.0f / D_MODEL) + RMS_EPS);
    out[(size_t)row * D_MODEL + tid] = v * r * w[tid];
}

// -------------------- tf32 mma GEMM: C = A @ W^T (+res) --------------------
// A: [M,K] rm, W: [N,K] rm. Block tile 128x128, BK=32, 8 warps = 2x4, warp 64x32.
#define GSTR 36  // smem row stride in words (conflict-free: bank = 4*grp + qd)

__device__ __forceinline__ void mma_gemm_core(const float* __restrict__ A,
                                              const float* __restrict__ W,
                                              const float* __restrict__ res,
                                              float* __restrict__ C,
                                              int N, int K,
                                              uint32_t* As, uint32_t* Bs) {
    const int tid = threadIdx.x;
    const int lane = tid & 31, w = tid >> 5;
    const int grp = lane >> 2, qd = lane & 3;
    const int wm = (w >> 2) * 64, wn = (w & 3) * 32;
    const int bm = blockIdx.x * 128, bn = blockIdx.y * 128;

    float acc[4][4][4];
#pragma unroll
    for (int mt = 0; mt < 4; mt++)
#pragma unroll
        for (int nt = 0; nt < 4; nt++)
#pragma unroll
            for (int j = 0; j < 4; j++) acc[mt][nt][j] = 0.f;

    const int lrow = tid >> 3;          // 0..31
    const int lc4 = (tid & 7) << 2;     // 0,4,...,28

    for (int k0 = 0; k0 < K; k0 += 32) {
        __syncthreads();
#pragma unroll
        for (int i = 0; i < 4; i++) {
            const int row = lrow + i * 32;
            const float4 av = *(const float4*)&A[(size_t)(bm + row) * K + k0 + lc4];
            uint4 ua;
            ua.x = f2tf(av.x); ua.y = f2tf(av.y); ua.z = f2tf(av.z); ua.w = f2tf(av.w);
            *(uint4*)&As[row * GSTR + lc4] = ua;
            const float4 wv = *(const float4*)&W[(size_t)(bn + row) * K + k0 + lc4];
            uint4 ub;
            ub.x = f2tf(wv.x); ub.y = f2tf(wv.y); ub.z = f2tf(wv.z); ub.w = f2tf(wv.w);
            *(uint4*)&Bs[row * GSTR + lc4] = ub;
        }
        __syncthreads();

#pragma unroll
        for (int kk = 0; kk < 4; kk++) {
            const int kb = kk * 8;
            uint32_t af[4][4], bf[4][2];
#pragma unroll
            for (int mt = 0; mt < 4; mt++) {
                const uint32_t* pa = &As[(wm + mt * 16 + grp) * GSTR + kb + qd];
                af[mt][0] = pa[0];
                af[mt][1] = pa[8 * GSTR];
                af[mt][2] = pa[4];
                af[mt][3] = pa[8 * GSTR + 4];
            }
#pragma unroll
            for (int nt = 0; nt < 4; nt++) {
                const uint32_t* pb = &Bs[(wn + nt * 8 + grp) * GSTR + kb + qd];
                bf[nt][0] = pb[0];
                bf[nt][1] = pb[4];
            }
#pragma unroll
            for (int mt = 0; mt < 4; mt++)
#pragma unroll
                for (int nt = 0; nt < 4; nt++)
                    mma8(acc[mt][nt], af[mt][0], af[mt][1], af[mt][2], af[mt][3],
                         bf[nt][0], bf[nt][1]);
        }
    }

    // epilogue
#pragma unroll
    for (int mt = 0; mt < 4; mt++) {
        const int r0 = bm + wm + mt * 16 + grp;
#pragma unroll
        for (int nt = 0; nt < 4; nt++) {
            const int c = bn + wn + nt * 8 + 2 * qd;
            float2 v0 = make_float2(acc[mt][nt][0], acc[mt][nt][1]);
            float2 v1 = make_float2(acc[mt][nt][2], acc[mt][nt][3]);
            if (res) {
                float2 rr = *(const float2*)&res[(size_t)r0 * N + c];
                v0.x += rr.x; v0.y += rr.y;
                rr = *(const float2*)&res[(size_t)(r0 + 8) * N + c];
                v1.x += rr.x; v1.y += rr.y;
            }
            *(float2*)&C[(size_t)r0 * N + c] = v0;
            *(float2*)&C[(size_t)(r0 + 8) * N + c] = v1;
        }
    }
}

__global__ void __launch_bounds__(256, 2) qkv_gemm_kernel(
    const float* __restrict__ h,
    const float* __restrict__ wq, const float* __restrict__ wk, const float* __restrict__ wv,
    float* __restrict__ q, float* __restrict__ k, float* __restrict__ v) {
    __shared__ uint32_t As[128 * GSTR];
    __shared__ uint32_t Bs[128 * GSTR];
    const float* W;
    float* C;
    if (blockIdx.z == 0) { W = wq; C = q; }
    else if (blockIdx.z == 1) { W = wk; C = k; }
    else { W = wv; C = v; }
    mma_gemm_core(h, W, nullptr, C, D_MODEL, D_MODEL, As, Bs);
}

__global__ void __launch_bounds__(256, 2) res_gemm_kernel(
    const float* __restrict__ A, const float* __restrict__ W,
    const float* __restrict__ res, float* __restrict__ C, int N, int K) {
    __shared__ uint32_t As[128 * GSTR];
    __shared__ uint32_t Bs[128 * GSTR];
    mma_gemm_core(A, W, res, C, N, K, As, Bs);
}

__global__ void __launch_bounds__(256, 2) gateup_gemm_kernel(
    const float* __restrict__ hf,
    const float* __restrict__ wg, const float* __restrict__ wu,
    float* __restrict__ gate, float* __restrict__ up) {
    __shared__ uint32_t As[128 * GSTR];
    __shared__ uint32_t Bs[128 * GSTR];
    const float* W = (blockIdx.z == 0) ? wg : wu;
    float* C = (blockIdx.z == 0) ? gate : up;
    mma_gemm_core(hf, W, nullptr, C, D_FF, D_MODEL, As, Bs);
}

// -------------------- flash attention, tf32 mma --------------------
// Q/K/V layout [B*T, 256], head h at cols [h*64, h*64+64).
// Block: 128 q-rows, 8 warps (16 rows each), kv tiles of 64.
#define QSTR 72   // Qs/Ks/Vs row stride (words)
#define PSTR 68   // Ps row stride (words)

__global__ void __launch_bounds__(256, 2) flash_mma_kernel(const float* __restrict__ Q,
                                                           const float* __restrict__ K,
                                                           const float* __restrict__ V,
                                                           float* __restrict__ O) {
    extern __shared__ uint32_t sm[];
    uint32_t* Qs = sm;                    // [128][72]
    uint32_t* Ks = Qs + 128 * QSTR;       // [64][72]
    uint32_t* Vs = Ks + 64 * QSTR;        // [64][72]
    uint32_t* Ps = Vs + 64 * QSTR;        // [8][16][68]

    const int qbi = blockIdx.x, h = blockIdx.y, b = blockIdx.z;
    const int tid = threadIdx.x;
    const int lane = tid & 31, w = tid >> 5;
    const int grp = lane >> 2, qd = lane & 3;
    const int q0 = qbi * 128;
    const int qw = q0 + w * 16;
    const size_t base = ((size_t)b * T_) * D_MODEL + h * 64;

    // load Q tile (row-major, tf32)
#pragma unroll
    for (int i = 0; i < 8; i++) {
        const int idx = tid + i * 256;
        const int m = idx >> 4, d4 = (idx & 15) << 2;
        const float4 qv = *(const float4*)&Q[base + (size_t)(q0 + m) * D_MODEL + d4];
        uint4 u;
        u.x = f2tf(qv.x); u.y = f2tf(qv.y); u.z = f2tf(qv.z); u.w = f2tf(qv.w);
        *(uint4*)&Qs[m * QSTR + d4] = u;
    }

    float o[8][4];
    float mi0 = -1e30f, mi1 = -1e30f, li0 = 0.f, li1 = 0.f;
#pragma unroll
    for (int nt = 0; nt < 8; nt++)
#pragma unroll
        for (int j = 0; j < 4; j++) o[nt][j] = 0.f;

    uint32_t* PsW = Ps + w * 16 * PSTR;
    const int ntiles = 2 * qbi + 2;

    for (int kt = 0; kt < ntiles; kt++) {
        const int k0 = kt * 64;
        __syncthreads();  // previous PV done reading Ks/Vs
#pragma unroll
        for (int i = 0; i < 4; i++) {
            const int idx = tid + i * 256;
            const int key = idx >> 4, d4 = (idx & 15) << 2;
            const float4 kv = *(const float4*)&K[base + (size_t)(k0 + key) * D_MODEL + d4];
            uint4 uk;
            uk.x = f2tf(kv.x); uk.y = f2tf(kv.y); uk.z = f2tf(kv.z); uk.w = f2tf(kv.w);
            *(uint4*)&Ks[key * QSTR + d4] = uk;
            const float4 vv = *(const float4*)&V[base + (size_t)(k0 + key) * D_MODEL + d4];
            uint4 uv;
            uv.x = f2tf(vv.x); uv.y = f2tf(vv.y); uv.z = f2tf(vv.z); uv.w = f2tf(vv.w);
            *(uint4*)&Vs[key * QSTR + d4] = uv;
        }
        __syncthreads();

        if (k0 <= qw + 15) {  // warp not fully masked
            // S = Q K^T  (16 x 64 per warp)
            float s[8][4];
#pragma unroll
            for (int nt = 0; nt < 8; nt++)
#pragma unroll
                for (int j = 0; j < 4; j++) s[nt][j] = 0.f;

#pragma unroll
            for (int kk = 0; kk < 8; kk++) {
                const int kb = kk * 8;
                const uint32_t* pa = &Qs[(w * 16 + grp) * QSTR + kb + qd];
                const uint32_t a0 = pa[0];
                const uint32_t a1 = pa[8 * QSTR];
                const uint32_t a2 = pa[4];
                const uint32_t a3 = pa[8 * QSTR + 4];
#pragma unroll
                for (int nt = 0; nt < 8; nt++) {
                    const uint32_t* pb = &Ks[(nt * 8 + grp) * QSTR + kb + qd];
                    mma8(s[nt], a0, a1, a2, a3, pb[0], pb[4]);
                }
            }

            // scale + causal mask
            const int r0 = qw + grp, r1 = r0 + 8;
            const float sc = 0.125f;
#pragma unroll
            for (int nt = 0; nt < 8; nt++)
#pragma unroll
                for (int j = 0; j < 4; j++) s[nt][j] *= sc;
            if (k0 + 63 > qw) {
#pragma unroll
                for (int nt = 0; nt < 8; nt++) {
                    const int c0 = k0 + nt * 8 + 2 * qd;
                    if (c0 > r0) s[nt][0] = -1e30f;
                    if (c0 + 1 > r0) s[nt][1] = -1e30f;
                    if (c0 > r1) s[nt][2] = -1e30f;
                    if (c0 + 1 > r1) s[nt][3] = -1e30f;
                }
            }

            // online softmax (rows r0, r1; 4-lane groups share a row)
            float mx0 = -1e30f, mx1 = -1e30f;
#pragma unroll
            for (int nt = 0; nt < 8; nt++) {
                mx0 = fmaxf(mx0, fmaxf(s[nt][0], s[nt][1]));
                mx1 = fmaxf(mx1, fmaxf(s[nt][2], s[nt][3]));
            }
            mx0 = fmaxf(mx0, __shfl_xor_sync(0xffffffffu, mx0, 1));
            mx0 = fmaxf(mx0, __shfl_xor_sync(0xffffffffu, mx0, 2));
            mx1 = fmaxf(mx1, __shfl_xor_sync(0xffffffffu, mx1, 1));
            mx1 = fmaxf(mx1, __shfl_xor_sync(0xffffffffu, mx1, 2));

            const float nm0 = fmaxf(mi0, mx0), nm1 = fmaxf(mi1, mx1);
            const float al0 = __expf(mi0 - nm0), al1 = __expf(mi1 - nm1);
            mi0 = nm0; mi1 = nm1;

            float sum0 = 0.f, sum1 = 0.f;
#pragma unroll
            for (int nt = 0; nt < 8; nt++) {
                const float p0 = __expf(s[nt][0] - nm0);
                const float p1 = __expf(s[nt][1] - nm0);
                const float p2 = __expf(s[nt][2] - nm1);
                const float p3 = __expf(s[nt][3] - nm1);
                sum0 += p0 + p1;
                sum1 += p2 + p3;
                uint2 u0 = make_uint2(f2tf(p0), f2tf(p1));
                uint2 u1 = make_uint2(f2tf(p2), f2tf(p3));
                *(uint2*)&PsW[grp * PSTR + nt * 8 + 2 * qd] = u0;
                *(uint2*)&PsW[(grp + 8) * PSTR + nt * 8 + 2 * qd] = u1;
            }
            sum0 += __shfl_xor_sync(0xffffffffu, sum0, 1);
            sum0 += __shfl_xor_sync(0xffffffffu, sum0, 2);
            sum1 += __shfl_xor_sync(0xffffffffu, sum1, 1);
            sum1 += __shfl_xor_sync(0xffffffffu, sum1, 2);
            li0 = li0 * al0 + sum0;
            li1 = li1 * al1 + sum1;
#pragma unroll
            for (int nt = 0; nt < 8; nt++) {
                o[nt][0] *= al0; o[nt][1] *= al0;
                o[nt][2] *= al1; o[nt][3] *= al1;
            }
            __syncwarp();

            // O += P @ V  (k-dim = 64 keys)
#pragma unroll
            for (int ks = 0; ks < 8; ks++) {
                const int kb = ks * 8;
                const uint32_t* pa = &PsW[grp * PSTR + kb + qd];
                const uint32_t a0 = pa[0];
                const uint32_t a1 = pa[8 * PSTR];
                const uint32_t a2 = pa[4];
                const uint32_t a3 = pa[8 * PSTR + 4];
#pragma unroll
                for (int nt = 0; nt < 8; nt++) {
                    const uint32_t* pb = &Vs[(kb + qd) * QSTR + nt * 8 + grp];
                    mma8(o[nt], a0, a1, a2, a3, pb[0], pb[4 * QSTR]);
                }
            }
        }
    }

    // epilogue
    const int r0 = qw + grp;
    const float inv0 = 1.0f / li0, inv1 = 1.0f / li1;
#pragma unroll
    for (int nt = 0; nt < 8; nt++) {
        const int c = nt * 8 + 2 * qd;
        float2 v0 = make_float2(o[nt][0] * inv0, o[nt][1] * inv0);
        float2 v1 = make_float2(o[nt][2] * inv1, o[nt][3] * inv1);
        *(float2*)&O[base + (size_t)r0 * D_MODEL + c] = v0;
        *(float2*)&O[base + (size_t)(r0 + 8) * D_MODEL + c] = v1;
    }
}

// -------------------- silu(gate) * up --------------------
__global__ void silu_mul_kernel(const float* __restrict__ g, const float* __restrict__ u,
                                float* __restrict__ out, int n) {
    int i = blockIdx.x * blockDim.x + threadIdx.x;
    if (i < n) {
        float x = g[i];
        out[i] = (x / (1.0f + __expf(-x))) * u[i];
    }
}

// -------------------- launch --------------------
extern "C" void kernel_launch(void* const* d_in, const int* in_sizes, int n_in,
                              void* d_out, int out_size) {
    const float* x          = (const float*)d_in[0];
    // d_in[1] = causal_mask (bool) — handled analytically
    const float* rms_attn_w = (const float*)d_in[2];
    const float* wq         = (const float*)d_in[3];
    const float* wk         = (const float*)d_in[4];
    const float* wv         = (const float*)d_in[5];
    const float* wo         = (const float*)d_in[6];
    const float* rms_ffn_w  = (const float*)d_in[7];
    const float* wg         = (const float*)d_in[8];
    const float* wu         = (const float*)d_in[9];
    const float* wd         = (const float*)d_in[10];
    float* out = (float*)d_out;

    float *h, *q, *k, *v, *x1, *hf, *gate, *up;
    cudaGetSymbolAddress((void**)&h, g_h);
    cudaGetSymbolAddress((void**)&q, g_q);
    cudaGetSymbolAddress((void**)&k, g_k);
    cudaGetSymbolAddress((void**)&v, g_v);
    cudaGetSymbolAddress((void**)&x1, g_x1);
    cudaGetSymbolAddress((void**)&hf, g_hf);
    cudaGetSymbolAddress((void**)&gate, g_gate);
    cudaGetSymbolAddress((void**)&up, g_up);

    const int FLASH_SMEM = (128 * QSTR + 64 * QSTR + 64 * QSTR + 8 * 16 * PSTR) * 4;  // 108544
    cudaFuncSetAttribute(flash_mma_kernel, cudaFuncAttributeMaxDynamicSharedMemorySize, FLASH_SMEM);

    // 1. h = rmsnorm(x)
    rmsnorm_kernel<<<BT, 256>>>(x, rms_attn_w, h);
    // 2. q,k,v
    qkv_gemm_kernel<<<dim3(BT / 128, D_MODEL / 128, 3), 256>>>(h, wq, wk, wv, q, k, v);
    // 3. attention → h
    flash_mma_kernel<<<dim3(T_ / 128, 4, B_), 256, FLASH_SMEM>>>(q, k, v, h);
    // 4. x1 = x + attn @ wo^T
    res_gemm_kernel<<<dim3(BT / 128, D_MODEL / 128), 256>>>(h, wo, x, x1, D_MODEL, D_MODEL);
    // 5. hf = rmsnorm(x1)
    rmsnorm_kernel<<<BT, 256>>>(x1, rms_ffn_w, hf);
    // 6. gate, up
    gateup_gemm_kernel<<<dim3(BT / 128, D_FF / 128, 2), 256>>>(hf, wg, wu, gate, up);
    // 7. gate = silu(gate) * up
    silu_mul_kernel<<<(BT * D_FF) / 256, 256>>>(gate, up, gate, BT * D_FF);
    // 8. out = x1 + gate @ wd^T
    res_gemm_kernel<<<dim3(BT / 128, D_MODEL / 128), 256>>>(gate, wd, x1, out, D_MODEL, D_FF);
}

// round 3
// speedup vs baseline: 5.6833x; 2.2118x over previous
#include <cuda_runtime.h>
#include <cuda_bf16.h>
#include <stdint.h>
#include <math.h>

#define D_MODEL 256
#define D_FF    1024
#define T_      2048
#define B_      4
#define BT      8192
#define RMS_EPS 1e-5f

typedef __nv_bfloat16 bf16;

// -------------------- scratch (no allocs allowed) --------------------
// weight bf16 pool: wq@0 wk@65536 wv@131072 wo@196608 wg@262144 wu@524288 wd@786432
__device__ bf16  g_w16[1048576];
__device__ bf16  g_h16[BT * D_MODEL];    // rmsnorm out (attn), reused for ffn norm
__device__ bf16  g_q16[BT * D_MODEL];
__device__ bf16  g_k16[BT * D_MODEL];
__device__ bf16  g_vt16[BT * D_MODEL];   // v transposed: [(b*4+h)*64+d][t]
__device__ bf16  g_attn16[BT * D_MODEL];
__device__ bf16  g_silu16[BT * D_FF];
__device__ float g_x1[BT * D_MODEL];

// -------------------- helpers --------------------
__device__ __forceinline__ uint32_t pkbf(float lo, float hi) {
    uint32_t r;
    asm("cvt.rn.bf16x2.f32 %0,%1,%2;" : "=r"(r) : "f"(hi), "f"(lo));
    return r;
}
__device__ __forceinline__ void mma16(float* d, uint32_t a0, uint32_t a1, uint32_t a2,
                                      uint32_t a3, uint32_t b0, uint32_t b1) {
    asm volatile(
        "mma.sync.aligned.m16n8k16.row.col.f32.bf16.bf16.f32 "
        "{%0,%1,%2,%3},{%4,%5,%6,%7},{%8,%9},{%0,%1,%2,%3};"
        : "+f"(d[0]), "+f"(d[1]), "+f"(d[2]), "+f"(d[3])
        : "r"(a0), "r"(a1), "r"(a2), "r"(a3), "r"(b0), "r"(b1));
}
__device__ __forceinline__ uint32_t s2u(const void* p) {
    return (uint32_t)__cvta_generic_to_shared(p);
}
__device__ __forceinline__ void cp16(uint32_t s, const void* g) {
    asm volatile("cp.async.cg.shared.global [%0],[%1],16;" :: "r"(s), "l"(g) : "memory");
}
#define CP_COMMIT asm volatile("cp.async.commit_group;" ::: "memory")
#define CP_WAIT0  asm volatile("cp.async.wait_group 0;" ::: "memory")

// -------------------- weight fp32 -> bf16 --------------------
__global__ void cvtw_kernel(const float* __restrict__ wq, const float* __restrict__ wk,
                            const float* __restrict__ wv, const float* __restrict__ wo,
                            const float* __restrict__ wg, const float* __restrict__ wu,
                            const float* __restrict__ wd) {
    const float* src; int n, off;
    switch (blockIdx.y) {
        case 0: src = wq; n = 65536;  off = 0;      break;
        case 1: src = wk; n = 65536;  off = 65536;  break;
        case 2: src = wv; n = 65536;  off = 131072; break;
        case 3: src = wo; n = 65536;  off = 196608; break;
        case 4: src = wg; n = 262144; off = 262144; break;
        case 5: src = wu; n = 262144; off = 524288; break;
        default: src = wd; n = 262144; off = 786432; break;
    }
    const int i = (blockIdx.x * 256 + threadIdx.x) * 4;
    if (i < n) {
        const float4 v = *(const float4*)(src + i);
        uint2 u = make_uint2(pkbf(v.x, v.y), pkbf(v.z, v.w));
        *(uint2*)&g_w16[off + i] = u;
    }
}

// -------------------- rmsnorm -> bf16 into g_h16 --------------------
__global__ void rmsnorm_kernel(const float* __restrict__ x, const float* __restrict__ w) {
    const int row = blockIdx.x;
    const int tid = threadIdx.x;
    const float v = x[(size_t)row * D_MODEL + tid];
    float ss = v * v;
#pragma unroll
    for (int m = 16; m; m >>= 1) ss += __shfl_xor_sync(0xffffffffu, ss, m);
    __shared__ float ws[8];
    __shared__ float s_tot;
    if ((tid & 31) == 0) ws[tid >> 5] = ss;
    __syncthreads();
    if (tid < 8) {
        float t = ws[tid];
        t += __shfl_xor_sync(0xffu, t, 4);
        t += __shfl_xor_sync(0xffu, t, 2);
        t += __shfl_xor_sync(0xffu, t, 1);
        if (tid == 0) s_tot = t;
    }
    __syncthreads();
    const float r = rsqrtf(s_tot * (1.0f / D_MODEL) + RMS_EPS);
    g_h16[(size_t)row * D_MODEL + tid] = __float2bfloat16(v * r * w[tid]);
}

// -------------------- bf16 GEMM core: BM=64 BN=128 BK=32, cp.async 2-stage ---
// A:[M,K] rm bf16, W:[N,K] rm bf16. smem rows: 32 halves = 16 words, XOR swizzle
// chunk' = c ^ ((row>>1)&3). acc[2][4][4], warps 2(M)x4(N), warp tile 32x32.
__device__ __forceinline__ void gemm_core(const bf16* __restrict__ A,
                                          const bf16* __restrict__ W,
                                          int K, uint32_t* As, uint32_t* Bs,
                                          float (&acc)[2][4][4]) {
    const int tid = threadIdx.x, lane = tid & 31, w = tid >> 5;
    const int grp = lane >> 2, qd = lane & 3;
    const int bm = blockIdx.x * 64, bn = blockIdx.y * 128;
    const int wm = (w & 1) * 32, wn = (w >> 1) * 32;

#pragma unroll
    for (int mt = 0; mt < 2; mt++)
#pragma unroll
        for (int nt = 0; nt < 4; nt++)
#pragma unroll
            for (int j = 0; j < 4; j++) acc[mt][nt][j] = 0.f;

    const int ar = tid >> 2, ac = tid & 3;
    const bf16* ga  = A + (size_t)(bm + ar) * K + ac * 8;
    const bf16* gb0 = W + (size_t)(bn + ar) * K + ac * 8;
    const bf16* gb1 = gb0 + (size_t)64 * K;
    const uint32_t off = ((ar * 16 + ((ac ^ ((ar >> 1) & 3)) << 2)) << 2);
    const uint32_t sa = s2u(As) + off;
    const uint32_t sb = s2u(Bs) + off;

    const int NK = K >> 5;
    cp16(sa, ga); cp16(sb, gb0); cp16(sb + 4096, gb1);
    CP_COMMIT;

    for (int it = 0; it < NK; ++it) {
        CP_WAIT0;
        __syncthreads();
        if (it + 1 < NK) {
            const int st = (it + 1) & 1;
            const int ko = (it + 1) << 5;
            cp16(sa + st * 4096, ga + ko);
            cp16(sb + st * 8192, gb0 + ko);
            cp16(sb + st * 8192 + 4096, gb1 + ko);
            CP_COMMIT;
        }
        const uint32_t* Ab = As + (it & 1) * 1024;
        const uint32_t* Bb = Bs + (it & 1) * 2048;
#pragma unroll
        for (int kb = 0; kb < 2; ++kb) {
            uint32_t af[2][4], bfr[4][2];
#pragma unroll
            for (int mt = 0; mt < 2; ++mt) {
                const int R = wm + mt * 16 + grp;
                const int sw = (R >> 1) & 3;
                const uint32_t* p = Ab + R * 16 + qd;
                af[mt][0] = p[((kb * 2) ^ sw) << 2];
                af[mt][1] = p[128 + (((kb * 2) ^ sw) << 2)];
                af[mt][2] = p[((kb * 2 + 1) ^ sw) << 2];
                af[mt][3] = p[128 + (((kb * 2 + 1) ^ sw) << 2)];
            }
#pragma unroll
            for (int nt = 0; nt < 4; ++nt) {
                const int R = wn + nt * 8 + grp;
                const int sw = (R >> 1) & 3;
                const uint32_t* p = Bb + R * 16 + qd;
                bfr[nt][0] = p[((kb * 2) ^ sw) << 2];
                bfr[nt][1] = p[((kb * 2 + 1) ^ sw) << 2];
            }
#pragma unroll
            for (int mt = 0; mt < 2; ++mt)
#pragma unroll
                for (int nt = 0; nt < 4; ++nt)
                    mma16(acc[mt][nt], af[mt][0], af[mt][1], af[mt][2], af[mt][3],
                          bfr[nt][0], bfr[nt][1]);
        }
    }
}

// -------------------- qkv: h16 @ {wq,wk,wv}^T -> q16/k16 (token-major), vt16 ----
__global__ void __launch_bounds__(256) qkv_kernel() {
    __shared__ uint32_t As[2 * 1024];
    __shared__ uint32_t Bs[2 * 2048];
    const bf16* W = g_w16 + blockIdx.z * 65536;
    float acc[2][4][4];
    gemm_core(g_h16, W, D_MODEL, As, Bs, acc);

    const int tid = threadIdx.x, lane = tid & 31, w = tid >> 5;
    const int grp = lane >> 2, qd = lane & 3;
    const int bm = blockIdx.x * 64, bn = blockIdx.y * 128;
    const int wm = (w & 1) * 32, wn = (w >> 1) * 32;

    if (blockIdx.z < 2) {
        bf16* C = (blockIdx.z == 0) ? g_q16 : g_k16;
#pragma unroll
        for (int mt = 0; mt < 2; ++mt) {
            const int r0 = bm + wm + mt * 16 + grp;
#pragma unroll
            for (int nt = 0; nt < 4; ++nt) {
                const int c = bn + wn + nt * 8 + 2 * qd;
                *(uint32_t*)&C[(size_t)r0 * D_MODEL + c] = pkbf(acc[mt][nt][0], acc[mt][nt][1]);
                *(uint32_t*)&C[(size_t)(r0 + 8) * D_MODEL + c] = pkbf(acc[mt][nt][2], acc[mt][nt][3]);
            }
        }
    } else {
#pragma unroll
        for (int mt = 0; mt < 2; ++mt) {
            const int r0 = bm + wm + mt * 16 + grp;
            const int b0 = r0 >> 11, t0 = r0 & 2047;
            const int b1 = (r0 + 8) >> 11, t1 = (r0 + 8) & 2047;
#pragma unroll
            for (int nt = 0; nt < 4; ++nt) {
                const int c = bn + wn + nt * 8 + 2 * qd;
                const int hh = c >> 6, dd = c & 63;
                bf16* p0 = &g_vt16[((size_t)(b0 * 4 + hh) * 64 + dd) * T_ + t0];
                bf16* p1 = &g_vt16[((size_t)(b1 * 4 + hh) * 64 + dd) * T_ + t1];
                p0[0]  = __float2bfloat16(acc[mt][nt][0]);
                p0[T_] = __float2bfloat16(acc[mt][nt][1]);   // dd+1 row
                p1[0]  = __float2bfloat16(acc[mt][nt][2]);
                p1[T_] = __float2bfloat16(acc[mt][nt][3]);
            }
        }
    }
}

// -------------------- wo / down: A16 @ W^T + res -> fp32 (N=256) --------------
__global__ void __launch_bounds__(256) out_gemm_kernel(const bf16* __restrict__ A,
                                                       const bf16* __restrict__ W,
                                                       const float* __restrict__ res,
                                                       float* __restrict__ C, int K) {
    __shared__ uint32_t As[2 * 1024];
    __shared__ uint32_t Bs[2 * 2048];
    float acc[2][4][4];
    gemm_core(A, W, K, As, Bs, acc);

    const int tid = threadIdx.x, lane = tid & 31, w = tid >> 5;
    const int grp = lane >> 2, qd = lane & 3;
    const int bm = blockIdx.x * 64, bn = blockIdx.y * 128;
    const int wm = (w & 1) * 32, wn = (w >> 1) * 32;
#pragma unroll
    for (int mt = 0; mt < 2; ++mt) {
        const int r0 = bm + wm + mt * 16 + grp;
#pragma unroll
        for (int nt = 0; nt < 4; ++nt) {
            const int c = bn + wn + nt * 8 + 2 * qd;
            float2 v0 = make_float2(acc[mt][nt][0], acc[mt][nt][1]);
            float2 v1 = make_float2(acc[mt][nt][2], acc[mt][nt][3]);
            float2 rr = *(const float2*)&res[(size_t)r0 * D_MODEL + c];
            v0.x += rr.x; v0.y += rr.y;
            rr = *(const float2*)&res[(size_t)(r0 + 8) * D_MODEL + c];
            v1.x += rr.x; v1.y += rr.y;
            *(float2*)&C[(size_t)r0 * D_MODEL + c] = v0;
            *(float2*)&C[(size_t)(r0 + 8) * D_MODEL + c] = v1;
        }
    }
}

// -------------------- fused gate/up/silu: BM=64 BN=64, two B pipelines --------
__global__ void __launch_bounds__(256) gateup_kernel() {
    __shared__ uint32_t As[2 * 1024];
    __shared__ uint32_t Bg[2 * 1024];
    __shared__ uint32_t Bu[2 * 1024];
    const int tid = threadIdx.x, lane = tid & 31, w = tid >> 5;
    const int grp = lane >> 2, qd = lane & 3;
    const int bm = blockIdx.x * 64, bn = blockIdx.y * 64;
    const int wm = (w & 3) * 16, wn = (w >> 2) * 32;

    float ag[4][4], au[4][4];
#pragma unroll
    for (int nt = 0; nt < 4; nt++)
#pragma unroll
        for (int j = 0; j < 4; j++) { ag[nt][j] = 0.f; au[nt][j] = 0.f; }

    const bf16* Wg = g_w16 + 262144;
    const bf16* Wu = g_w16 + 524288;
    const int ar = tid >> 2, ac = tid & 3;
    const bf16* ga = g_h16 + (size_t)(bm + ar) * D_MODEL + ac * 8;
    const bf16* gg = Wg + (size_t)(bn + ar) * D_MODEL + ac * 8;
    const bf16* gu = Wu + (size_t)(bn + ar) * D_MODEL + ac * 8;
    const uint32_t off = ((ar * 16 + ((ac ^ ((ar >> 1) & 3)) << 2)) << 2);
    const uint32_t sa = s2u(As) + off, sg = s2u(Bg) + off, su = s2u(Bu) + off;

    cp16(sa, ga); cp16(sg, gg); cp16(su, gu);
    CP_COMMIT;

    const int NK = D_MODEL >> 5;  // 8
    for (int it = 0; it < NK; ++it) {
        CP_WAIT0;
        __syncthreads();
        if (it + 1 < NK) {
            const int st = (it + 1) & 1;
            const int ko = (it + 1) << 5;
            cp16(sa + st * 4096, ga + ko);
            cp16(sg + st * 4096, gg + ko);
            cp16(su + st * 4096, gu + ko);
            CP_COMMIT;
        }
        const uint32_t* Ab = As + (it & 1) * 1024;
        const uint32_t* Gb = Bg + (it & 1) * 1024;
        const uint32_t* Ub = Bu + (it & 1) * 1024;
#pragma unroll
        for (int kb = 0; kb < 2; ++kb) {
            const int R = wm + grp;
            const int sw = (R >> 1) & 3;
            const uint32_t* p = Ab + R * 16 + qd;
            const uint32_t a0 = p[((kb * 2) ^ sw) << 2];
            const uint32_t a1 = p[128 + (((kb * 2) ^ sw) << 2)];
            const uint32_t a2 = p[((kb * 2 + 1) ^ sw) << 2];
            const uint32_t a3 = p[128 + (((kb * 2 + 1) ^ sw) << 2)];
#pragma unroll
            for (int nt = 0; nt < 4; ++nt) {
                const int RB = wn + nt * 8 + grp;
                const int swb = (RB >> 1) & 3;
                const uint32_t x0 = ((kb * 2) ^ swb) << 2, x1 = ((kb * 2 + 1) ^ swb) << 2;
                const uint32_t* pg = Gb + RB * 16 + qd;
                const uint32_t* pu = Ub + RB * 16 + qd;
                mma16(ag[nt], a0, a1, a2, a3, pg[x0], pg[x1]);
                mma16(au[nt], a0, a1, a2, a3, pu[x0], pu[x1]);
            }
        }
    }

    const int r0 = bm + wm + grp;
#pragma unroll
    for (int nt = 0; nt < 4; ++nt) {
        const int c = bn + wn + nt * 8 + 2 * qd;
        float s0[4];
#pragma unroll
        for (int j = 0; j < 4; ++j) {
            const float g = ag[nt][j];
            s0[j] = (g / (1.0f + __expf(-g))) * au[nt][j];
        }
        *(uint32_t*)&g_silu16[(size_t)r0 * D_FF + c] = pkbf(s0[0], s0[1]);
        *(uint32_t*)&g_silu16[(size_t)(r0 + 8) * D_FF + c] = pkbf(s0[2], s0[3]);
    }
}

// -------------------- flash attention, bf16 mma, P in registers ---------------
// 128 q-rows/block, 8 warps (16 rows), kv tiles of 64, cp.async double-buffer.
// Qs rows 64 halves (8 chunks), swizzle chunk ^= (row&7).
__global__ void __launch_bounds__(256) flash_kernel() {
    __shared__ uint32_t Qs[128 * 32];      // 16KB
    __shared__ uint32_t Ks[2][64 * 32];    // 16KB
    __shared__ uint32_t Vs[2][64 * 32];    // 16KB
    const int qbi = blockIdx.x, h = blockIdx.y, b = blockIdx.z;
    const int tid = threadIdx.x, lane = tid & 31, w = tid >> 5;
    const int grp = lane >> 2, qd = lane & 3;
    const int q0 = qbi * 128;
    const int qw = q0 + w * 16;
    const size_t tok = (size_t)b * T_;
    const int bh = b * 4 + h;

    const bf16* Qg = g_q16 + (tok + q0) * D_MODEL + h * 64;
    const bf16* Kg = g_k16 + tok * D_MODEL + h * 64;
    const bf16* Vg = g_vt16 + (size_t)bh * 64 * T_;

    const uint32_t ksb = s2u(Ks), vsb = s2u(Vs);

    // issue kv tile 0
    {
#pragma unroll
        for (int i = 0; i < 2; ++i) {
            const int idx = tid + i * 256;
            const int r = idx >> 3, c = idx & 7;
            const uint32_t so = (r * 32 + ((c ^ (r & 7)) << 2)) << 2;
            cp16(ksb + so, Kg + (size_t)r * D_MODEL + c * 8);
            cp16(vsb + so, Vg + (size_t)r * T_ + c * 8);
        }
        CP_COMMIT;
    }
    // load Q
#pragma unroll
    for (int i = 0; i < 4; ++i) {
        const int idx = tid + i * 256;
        const int r = idx >> 3, c = idx & 7;
        const uint4 v = *(const uint4*)(Qg + (size_t)r * D_MODEL + c * 8);
        *(uint4*)&Qs[r * 32 + ((c ^ (r & 7)) << 2)] = v;
    }

    float o[8][4];
    float mi0 = -1e30f, mi1 = -1e30f, li0 = 0.f, li1 = 0.f;
#pragma unroll
    for (int nt = 0; nt < 8; nt++)
#pragma unroll
        for (int j = 0; j < 4; j++) o[nt][j] = 0.f;

    const int ntiles = 2 * qbi + 2;
    for (int kt = 0; kt < ntiles; ++kt) {
        const int k0 = kt * 64;
        CP_WAIT0;
        __syncthreads();
        if (kt + 1 < ntiles) {
            const int st = (kt + 1) & 1;
            const int kn = (kt + 1) * 64;
#pragma unroll
            for (int i = 0; i < 2; ++i) {
                const int idx = tid + i * 256;
                const int r = idx >> 3, c = idx & 7;
                const uint32_t so = ((r * 32 + ((c ^ (r & 7)) << 2)) << 2) + st * 8192;
                cp16(ksb + so, Kg + (size_t)(kn + r) * D_MODEL + c * 8);
                cp16(vsb + so, Vg + (size_t)r * T_ + kn + c * 8);
            }
            CP_COMMIT;
        }
        if (k0 > qw + 15) continue;
        const uint32_t* Kb = Ks[kt & 1];
        const uint32_t* Vb = Vs[kt & 1];

        // ---- S = Q K^T (warp: 16 x 64) ----
        float s[8][4];
#pragma unroll
        for (int nt = 0; nt < 8; nt++)
#pragma unroll
            for (int j = 0; j < 4; j++) s[nt][j] = 0.f;
#pragma unroll
        for (int kb = 0; kb < 4; ++kb) {
            const uint32_t* pq = Qs + (w * 16 + grp) * 32 + qd;
            const uint32_t x0 = ((kb * 2) ^ grp) << 2, x1 = ((kb * 2 + 1) ^ grp) << 2;
            const uint32_t a0 = pq[x0], a1 = pq[256 + x0];
            const uint32_t a2 = pq[x1], a3 = pq[256 + x1];
#pragma unroll
            for (int nt = 0; nt < 8; ++nt) {
                const uint32_t* pkk = Kb + (nt * 8 + grp) * 32 + qd;
                mma16(s[nt], a0, a1, a2, a3, pkk[x0], pkk[x1]);
            }
        }

        // ---- scale + causal mask ----
        const int r0 = qw + grp, r1 = r0 + 8;
#pragma unroll
        for (int nt = 0; nt < 8; nt++)
#pragma unroll
            for (int j = 0; j < 4; j++) s[nt][j] *= 0.125f;
        if (k0 + 63 > qw) {
#pragma unroll
            for (int nt = 0; nt < 8; nt++) {
                const int c0 = k0 + nt * 8 + 2 * qd;
                if (c0 > r0) s[nt][0] = -1e30f;
                if (c0 + 1 > r0) s[nt][1] = -1e30f;
                if (c0 > r1) s[nt][2] = -1e30f;
                if (c0 + 1 > r1) s[nt][3] = -1e30f;
            }
        }

        // ---- online softmax ----
        float mx0 = -1e30f, mx1 = -1e30f;
#pragma unroll
        for (int nt = 0; nt < 8; nt++) {
            mx0 = fmaxf(mx0, fmaxf(s[nt][0], s[nt][1]));
            mx1 = fmaxf(mx1, fmaxf(s[nt][2], s[nt][3]));
        }
        mx0 = fmaxf(mx0, __shfl_xor_sync(0xffffffffu, mx0, 1));
        mx0 = fmaxf(mx0, __shfl_xor_sync(0xffffffffu, mx0, 2));
        mx1 = fmaxf(mx1, __shfl_xor_sync(0xffffffffu, mx1, 1));
        mx1 = fmaxf(mx1, __shfl_xor_sync(0xffffffffu, mx1, 2));
        const float nm0 = fmaxf(mi0, mx0), nm1 = fmaxf(mi1, mx1);
        const float al0 = __expf(mi0 - nm0), al1 = __expf(mi1 - nm1);
        mi0 = nm0; mi1 = nm1;

        float sum0 = 0.f, sum1 = 0.f;
#pragma unroll
        for (int nt = 0; nt < 8; nt++) {
            s[nt][0] = __expf(s[nt][0] - nm0);
            s[nt][1] = __expf(s[nt][1] - nm0);
            s[nt][2] = __expf(s[nt][2] - nm1);
            s[nt][3] = __expf(s[nt][3] - nm1);
            sum0 += s[nt][0] + s[nt][1];
            sum1 += s[nt][2] + s[nt][3];
        }
        sum0 += __shfl_xor_sync(0xffffffffu, sum0, 1);
        sum0 += __shfl_xor_sync(0xffffffffu, sum0, 2);
        sum1 += __shfl_xor_sync(0xffffffffu, sum1, 1);
        sum1 += __shfl_xor_sync(0xffffffffu, sum1, 2);
        li0 = li0 * al0 + sum0;
        li1 = li1 * al1 + sum1;

        // pack P into A-fragments (registers only)
        uint32_t pa[4][4];
#pragma unroll
        for (int ks = 0; ks < 4; ++ks) {
            pa[ks][0] = pkbf(s[2 * ks][0], s[2 * ks][1]);
            pa[ks][1] = pkbf(s[2 * ks][2], s[2 * ks][3]);
            pa[ks][2] = pkbf(s[2 * ks + 1][0], s[2 * ks + 1][1]);
            pa[ks][3] = pkbf(s[2 * ks + 1][2], s[2 * ks + 1][3]);
        }
#pragma unroll
        for (int nt = 0; nt < 8; nt++) {
            o[nt][0] *= al0; o[nt][1] *= al0;
            o[nt][2] *= al1; o[nt][3] *= al1;
        }

        // ---- O += P @ V ----
#pragma unroll
        for (int ks = 0; ks < 4; ++ks) {
            const uint32_t x0 = ((ks * 2) ^ grp) << 2, x1 = ((ks * 2 + 1) ^ grp) << 2;
#pragma unroll
            for (int nt = 0; nt < 8; ++nt) {
                const uint32_t* pv = Vb + (nt * 8 + grp) * 32 + qd;
                mma16(o[nt], pa[ks][0], pa[ks][1], pa[ks][2], pa[ks][3], pv[x0], pv[x1]);
            }
        }
    }

    // epilogue -> attn16 [token][256]
    const float inv0 = 1.0f / li0, inv1 = 1.0f / li1;
    const int r0 = qw + grp;
#pragma unroll
    for (int nt = 0; nt < 8; ++nt) {
        const int c = h * 64 + nt * 8 + 2 * qd;
        *(uint32_t*)&g_attn16[(tok + r0) * D_MODEL + c] = pkbf(o[nt][0] * inv0, o[nt][1] * inv0);
        *(uint32_t*)&g_attn16[(tok + r0 + 8) * D_MODEL + c] = pkbf(o[nt][2] * inv1, o[nt][3] * inv1);
    }
}

// -------------------- launch --------------------
extern "C" void kernel_launch(void* const* d_in, const int* in_sizes, int n_in,
                              void* d_out, int out_size) {
    const float* x          = (const float*)d_in[0];
    const float* rms_attn_w = (const float*)d_in[2];
    const float* wq         = (const float*)d_in[3];
    const float* wk         = (const float*)d_in[4];
    const float* wv         = (const float*)d_in[5];
    const float* wo         = (const float*)d_in[6];
    const float* rms_ffn_w  = (const float*)d_in[7];
    const float* wg         = (const float*)d_in[8];
    const float* wu         = (const float*)d_in[9];
    const float* wd         = (const float*)d_in[10];
    float* out = (float*)d_out;

    bf16 *w16, *attn16, *silu16;
    float* x1;
    cudaGetSymbolAddress((void**)&w16, g_w16);
    cudaGetSymbolAddress((void**)&attn16, g_attn16);
    cudaGetSymbolAddress((void**)&silu16, g_silu16);
    cudaGetSymbolAddress((void**)&x1, g_x1);

    // 1. convert weights to bf16
    cvtw_kernel<<<dim3(256, 7), 256>>>(wq, wk, wv, wo, wg, wu, wd);
    // 2. h16 = rmsnorm(x)
    rmsnorm_kernel<<<BT, 256>>>(x, rms_attn_w);
    // 3. q,k,vt
    qkv_kernel<<<dim3(BT / 64, 2, 3), 256>>>();
    // 4. attention
    flash_kernel<<<dim3(T_ / 128, 4, B_), 256>>>();
    // 5. x1 = x + attn @ wo^T
    out_gemm_kernel<<<dim3(BT / 64, 2), 256>>>(attn16, w16 + 196608, x, x1, D_MODEL);
    // 6. h16 = rmsnorm(x1)
    rmsnorm_kernel<<<BT, 256>>>(x1, rms_ffn_w);
    // 7. silu16 = silu(h16@wg^T) * (h16@wu^T)
    gateup_kernel<<<dim3(BT / 64, D_FF / 64), 256>>>();
    // 8. out = x1 + silu16 @ wd^T
    out_gemm_kernel<<<dim3(BT / 64, 2), 256>>>(silu16, w16 + 786432, x1, out, D_FF);
}

// round 4
// speedup vs baseline: 6.8644x; 1.2078x over previous
#include <cuda_runtime.h>
#include <cuda_bf16.h>
#include <stdint.h>
#include <math.h>

#define D_MODEL 256
#define D_FF    1024
#define T_      2048
#define B_      4
#define BT      8192
#define RMS_EPS 1e-5f

typedef __nv_bfloat16 bf16;

// -------------------- scratch (no allocs allowed) --------------------
// weight bf16 pool: wq@0 wk@65536 wv@131072 wo@196608 wg@262144 wu@524288 wd@786432
__device__ bf16  g_w16[1048576];
__device__ bf16  g_h16[BT * D_MODEL];
__device__ bf16  g_q16[BT * D_MODEL];
__device__ bf16  g_k16[BT * D_MODEL];
__device__ bf16  g_vt16[BT * D_MODEL];   // v transposed: [(b*4+h)*64+d][t]
__device__ bf16  g_attn16[BT * D_MODEL];
__device__ bf16  g_silu16[BT * D_FF];
__device__ float g_x1[BT * D_MODEL];

// -------------------- helpers --------------------
__device__ __forceinline__ uint32_t pkbf(float lo, float hi) {
    uint32_t r;
    asm("cvt.rn.bf16x2.f32 %0,%1,%2;" : "=r"(r) : "f"(hi), "f"(lo));
    return r;
}
__device__ __forceinline__ void mma16(float* d, uint32_t a0, uint32_t a1, uint32_t a2,
                                      uint32_t a3, uint32_t b0, uint32_t b1) {
    asm volatile(
        "mma.sync.aligned.m16n8k16.row.col.f32.bf16.bf16.f32 "
        "{%0,%1,%2,%3},{%4,%5,%6,%7},{%8,%9},{%0,%1,%2,%3};"
        : "+f"(d[0]), "+f"(d[1]), "+f"(d[2]), "+f"(d[3])
        : "r"(a0), "r"(a1), "r"(a2), "r"(a3), "r"(b0), "r"(b1));
}
__device__ __forceinline__ uint32_t s2u(const void* p) {
    return (uint32_t)__cvta_generic_to_shared(p);
}
__device__ __forceinline__ void cp16(uint32_t s, const void* g) {
    asm volatile("cp.async.cg.shared.global [%0],[%1],16;" :: "r"(s), "l"(g) : "memory");
}
#define CP_COMMIT asm volatile("cp.async.commit_group;" ::: "memory")
#define CP_WAIT0  asm volatile("cp.async.wait_group 0;" ::: "memory")

// -------------------- weight fp32 -> bf16 --------------------
__global__ void cvtw_kernel(const float* __restrict__ wq, const float* __restrict__ wk,
                            const float* __restrict__ wv, const float* __restrict__ wo,
                            const float* __restrict__ wg, const float* __restrict__ wu,
                            const float* __restrict__ wd) {
    const float* src; int n, off;
    switch (blockIdx.y) {
        case 0: src = wq; n = 65536;  off = 0;      break;
        case 1: src = wk; n = 65536;  off = 65536;  break;
        case 2: src = wv; n = 65536;  off = 131072; break;
        case 3: src = wo; n = 65536;  off = 196608; break;
        case 4: src = wg; n = 262144; off = 262144; break;
        case 5: src = wu; n = 262144; off = 524288; break;
        default: src = wd; n = 262144; off = 786432; break;
    }
    const int i = (blockIdx.x * 256 + threadIdx.x) * 4;
    if (i < n) {
        const float4 v = *(const float4*)(src + i);
        uint2 u = make_uint2(pkbf(v.x, v.y), pkbf(v.z, v.w));
        *(uint2*)&g_w16[off + i] = u;
    }
}

// -------------------- rmsnorm -> bf16 into g_h16 --------------------
__global__ void rmsnorm_kernel(const float* __restrict__ x, const float* __restrict__ w) {
    const int row = blockIdx.x;
    const int tid = threadIdx.x;
    const float v = x[(size_t)row * D_MODEL + tid];
    float ss = v * v;
#pragma unroll
    for (int m = 16; m; m >>= 1) ss += __shfl_xor_sync(0xffffffffu, ss, m);
    __shared__ float ws[8];
    __shared__ float s_tot;
    if ((tid & 31) == 0) ws[tid >> 5] = ss;
    __syncthreads();
    if (tid < 8) {
        float t = ws[tid];
        t += __shfl_xor_sync(0xffu, t, 4);
        t += __shfl_xor_sync(0xffu, t, 2);
        t += __shfl_xor_sync(0xffu, t, 1);
        if (tid == 0) s_tot = t;
    }
    __syncthreads();
    const float r = rsqrtf(s_tot * (1.0f / D_MODEL) + RMS_EPS);
    g_h16[(size_t)row * D_MODEL + tid] = __float2bfloat16(v * r * w[tid]);
}

// -------------------- bf16 GEMM core: BM=64 BN=128 BK=32, cp.async 2-stage ---
__device__ __forceinline__ void gemm_core(const bf16* __restrict__ A,
                                          const bf16* __restrict__ W,
                                          int K, uint32_t* As, uint32_t* Bs,
                                          float (&acc)[2][4][4]) {
    const int tid = threadIdx.x, lane = tid & 31, w = tid >> 5;
    const int grp = lane >> 2, qd = lane & 3;
    const int bm = blockIdx.x * 64, bn = blockIdx.y * 128;
    const int wm = (w & 1) * 32, wn = (w >> 1) * 32;

#pragma unroll
    for (int mt = 0; mt < 2; mt++)
#pragma unroll
        for (int nt = 0; nt < 4; nt++)
#pragma unroll
            for (int j = 0; j < 4; j++) acc[mt][nt][j] = 0.f;

    const int ar = tid >> 2, ac = tid & 3;
    const bf16* ga  = A + (size_t)(bm + ar) * K + ac * 8;
    const bf16* gb0 = W + (size_t)(bn + ar) * K + ac * 8;
    const bf16* gb1 = gb0 + (size_t)64 * K;
    const uint32_t off = ((ar * 16 + ((ac ^ ((ar >> 1) & 3)) << 2)) << 2);
    const uint32_t sa = s2u(As) + off;
    const uint32_t sb = s2u(Bs) + off;

    const int NK = K >> 5;
    cp16(sa, ga); cp16(sb, gb0); cp16(sb + 4096, gb1);
    CP_COMMIT;

    for (int it = 0; it < NK; ++it) {
        CP_WAIT0;
        __syncthreads();
        if (it + 1 < NK) {
            const int st = (it + 1) & 1;
            const int ko = (it + 1) << 5;
            cp16(sa + st * 4096, ga + ko);
            cp16(sb + st * 8192, gb0 + ko);
            cp16(sb + st * 8192 + 4096, gb1 + ko);
            CP_COMMIT;
        }
        const uint32_t* Ab = As + (it & 1) * 1024;
        const uint32_t* Bb = Bs + (it & 1) * 2048;
#pragma unroll
        for (int kb = 0; kb < 2; ++kb) {
            uint32_t af[2][4], bfr[4][2];
#pragma unroll
            for (int mt = 0; mt < 2; ++mt) {
                const int R = wm + mt * 16 + grp;
                const int sw = (R >> 1) & 3;
                const uint32_t* p = Ab + R * 16 + qd;
                af[mt][0] = p[((kb * 2) ^ sw) << 2];
                af[mt][1] = p[128 + (((kb * 2) ^ sw) << 2)];
                af[mt][2] = p[((kb * 2 + 1) ^ sw) << 2];
                af[mt][3] = p[128 + (((kb * 2 + 1) ^ sw) << 2)];
            }
#pragma unroll
            for (int nt = 0; nt < 4; ++nt) {
                const int R = wn + nt * 8 + grp;
                const int sw = (R >> 1) & 3;
                const uint32_t* p = Bb + R * 16 + qd;
                bfr[nt][0] = p[((kb * 2) ^ sw) << 2];
                bfr[nt][1] = p[((kb * 2 + 1) ^ sw) << 2];
            }
#pragma unroll
            for (int mt = 0; mt < 2; ++mt)
#pragma unroll
                for (int nt = 0; nt < 4; ++nt)
                    mma16(acc[mt][nt], af[mt][0], af[mt][1], af[mt][2], af[mt][3],
                          bfr[nt][0], bfr[nt][1]);
        }
    }
}

// -------------------- qkv --------------------
__global__ void __launch_bounds__(256) qkv_kernel() {
    __shared__ uint32_t As[2 * 1024];
    __shared__ uint32_t Bs[2 * 2048];
    const bf16* W = g_w16 + blockIdx.z * 65536;
    float acc[2][4][4];
    gemm_core(g_h16, W, D_MODEL, As, Bs, acc);

    const int tid = threadIdx.x, lane = tid & 31, w = tid >> 5;
    const int grp = lane >> 2, qd = lane & 3;
    const int bm = blockIdx.x * 64, bn = blockIdx.y * 128;
    const int wm = (w & 1) * 32, wn = (w >> 1) * 32;

    if (blockIdx.z < 2) {
        bf16* C = (blockIdx.z == 0) ? g_q16 : g_k16;
#pragma unroll
        for (int mt = 0; mt < 2; ++mt) {
            const int r0 = bm + wm + mt * 16 + grp;
#pragma unroll
            for (int nt = 0; nt < 4; ++nt) {
                const int c = bn + wn + nt * 8 + 2 * qd;
                *(uint32_t*)&C[(size_t)r0 * D_MODEL + c] = pkbf(acc[mt][nt][0], acc[mt][nt][1]);
                *(uint32_t*)&C[(size_t)(r0 + 8) * D_MODEL + c] = pkbf(acc[mt][nt][2], acc[mt][nt][3]);
            }
        }
    } else {
#pragma unroll
        for (int mt = 0; mt < 2; ++mt) {
            const int r0 = bm + wm + mt * 16 + grp;
            const int b0 = r0 >> 11, t0 = r0 & 2047;
            const int b1 = (r0 + 8) >> 11, t1 = (r0 + 8) & 2047;
#pragma unroll
            for (int nt = 0; nt < 4; ++nt) {
                const int c = bn + wn + nt * 8 + 2 * qd;
                const int hh = c >> 6, dd = c & 63;
                bf16* p0 = &g_vt16[((size_t)(b0 * 4 + hh) * 64 + dd) * T_ + t0];
                bf16* p1 = &g_vt16[((size_t)(b1 * 4 + hh) * 64 + dd) * T_ + t1];
                p0[0]  = __float2bfloat16(acc[mt][nt][0]);
                p0[T_] = __float2bfloat16(acc[mt][nt][1]);
                p1[0]  = __float2bfloat16(acc[mt][nt][2]);
                p1[T_] = __float2bfloat16(acc[mt][nt][3]);
            }
        }
    }
}

// -------------------- wo / down: A16 @ W^T + res -> fp32 (N=256) --------------
__global__ void __launch_bounds__(256) out_gemm_kernel(const bf16* __restrict__ A,
                                                       const bf16* __restrict__ W,
                                                       const float* __restrict__ res,
                                                       float* __restrict__ C, int K) {
    __shared__ uint32_t As[2 * 1024];
    __shared__ uint32_t Bs[2 * 2048];
    float acc[2][4][4];
    gemm_core(A, W, K, As, Bs, acc);

    const int tid = threadIdx.x, lane = tid & 31, w = tid >> 5;
    const int grp = lane >> 2, qd = lane & 3;
    const int bm = blockIdx.x * 64, bn = blockIdx.y * 128;
    const int wm = (w & 1) * 32, wn = (w >> 1) * 32;
#pragma unroll
    for (int mt = 0; mt < 2; ++mt) {
        const int r0 = bm + wm + mt * 16 + grp;
#pragma unroll
        for (int nt = 0; nt < 4; ++nt) {
            const int c = bn + wn + nt * 8 + 2 * qd;
            float2 v0 = make_float2(acc[mt][nt][0], acc[mt][nt][1]);
            float2 v1 = make_float2(acc[mt][nt][2], acc[mt][nt][3]);
            float2 rr = *(const float2*)&res[(size_t)r0 * D_MODEL + c];
            v0.x += rr.x; v0.y += rr.y;
            rr = *(const float2*)&res[(size_t)(r0 + 8) * D_MODEL + c];
            v1.x += rr.x; v1.y += rr.y;
            *(float2*)&C[(size_t)r0 * D_MODEL + c] = v0;
            *(float2*)&C[(size_t)(r0 + 8) * D_MODEL + c] = v1;
        }
    }
}

// -------------------- fused gate/up/silu --------------------
__global__ void __launch_bounds__(256) gateup_kernel() {
    __shared__ uint32_t As[2 * 1024];
    __shared__ uint32_t Bg[2 * 1024];
    __shared__ uint32_t Bu[2 * 1024];
    const int tid = threadIdx.x, lane = tid & 31, w = tid >> 5;
    const int grp = lane >> 2, qd = lane & 3;
    const int bm = blockIdx.x * 64, bn = blockIdx.y * 64;
    const int wm = (w & 3) * 16, wn = (w >> 2) * 32;

    float ag[4][4], au[4][4];
#pragma unroll
    for (int nt = 0; nt < 4; nt++)
#pragma unroll
        for (int j = 0; j < 4; j++) { ag[nt][j] = 0.f; au[nt][j] = 0.f; }

    const bf16* Wg = g_w16 + 262144;
    const bf16* Wu = g_w16 + 524288;
    const int ar = tid >> 2, ac = tid & 3;
    const bf16* ga = g_h16 + (size_t)(bm + ar) * D_MODEL + ac * 8;
    const bf16* gg = Wg + (size_t)(bn + ar) * D_MODEL + ac * 8;
    const bf16* gu = Wu + (size_t)(bn + ar) * D_MODEL + ac * 8;
    const uint32_t off = ((ar * 16 + ((ac ^ ((ar >> 1) & 3)) << 2)) << 2);
    const uint32_t sa = s2u(As) + off, sg = s2u(Bg) + off, su = s2u(Bu) + off;

    cp16(sa, ga); cp16(sg, gg); cp16(su, gu);
    CP_COMMIT;

    const int NK = D_MODEL >> 5;
    for (int it = 0; it < NK; ++it) {
        CP_WAIT0;
        __syncthreads();
        if (it + 1 < NK) {
            const int st = (it + 1) & 1;
            const int ko = (it + 1) << 5;
            cp16(sa + st * 4096, ga + ko);
            cp16(sg + st * 4096, gg + ko);
            cp16(su + st * 4096, gu + ko);
            CP_COMMIT;
        }
        const uint32_t* Ab = As + (it & 1) * 1024;
        const uint32_t* Gb = Bg + (it & 1) * 1024;
        const uint32_t* Ub = Bu + (it & 1) * 1024;
#pragma unroll
        for (int kb = 0; kb < 2; ++kb) {
            const int R = wm + grp;
            const int sw = (R >> 1) & 3;
            const uint32_t* p = Ab + R * 16 + qd;
            const uint32_t a0 = p[((kb * 2) ^ sw) << 2];
            const uint32_t a1 = p[128 + (((kb * 2) ^ sw) << 2)];
            const uint32_t a2 = p[((kb * 2 + 1) ^ sw) << 2];
            const uint32_t a3 = p[128 + (((kb * 2 + 1) ^ sw) << 2)];
#pragma unroll
            for (int nt = 0; nt < 4; ++nt) {
                const int RB = wn + nt * 8 + grp;
                const int swb = (RB >> 1) & 3;
                const uint32_t x0 = ((kb * 2) ^ swb) << 2, x1 = ((kb * 2 + 1) ^ swb) << 2;
                const uint32_t* pg = Gb + RB * 16 + qd;
                const uint32_t* pu = Ub + RB * 16 + qd;
                mma16(ag[nt], a0, a1, a2, a3, pg[x0], pg[x1]);
                mma16(au[nt], a0, a1, a2, a3, pu[x0], pu[x1]);
            }
        }
    }

    const int r0 = bm + wm + grp;
#pragma unroll
    for (int nt = 0; nt < 4; ++nt) {
        const int c = bn + wn + nt * 8 + 2 * qd;
        float s0[4];
#pragma unroll
        for (int j = 0; j < 4; ++j) {
            const float g = ag[nt][j];
            s0[j] = (g / (1.0f + __expf(-g))) * au[nt][j];
        }
        *(uint32_t*)&g_silu16[(size_t)r0 * D_FF + c] = pkbf(s0[0], s0[1]);
        *(uint32_t*)&g_silu16[(size_t)(r0 + 8) * D_FF + c] = pkbf(s0[2], s0[3]);
    }
}

// -------------------- flash attention, causal-balanced pairs ------------------
// Grid (8,4,4): block processes q-tile x (2x+2 ktiles) then 15-x (32-2x ktiles)
// => exactly 34 key-tiles per block. exp2-domain softmax.
#define LOG2E 1.4426950408889634f

__global__ void __launch_bounds__(256) flash_kernel() {
    __shared__ uint32_t Qs[128 * 32];
    __shared__ uint32_t Ks[2][64 * 32];
    __shared__ uint32_t Vs[2][64 * 32];
    const int xpair = blockIdx.x, h = blockIdx.y, b = blockIdx.z;
    const int tid = threadIdx.x, lane = tid & 31, w = tid >> 5;
    const int grp = lane >> 2, qd = lane & 3;
    const size_t tok = (size_t)b * T_;
    const int bh = b * 4 + h;
    const bf16* Kg = g_k16 + tok * D_MODEL + h * 64;
    const bf16* Vg = g_vt16 + (size_t)bh * 64 * T_;
    const uint32_t ksb = s2u(Ks), vsb = s2u(Vs);

    for (int rep = 0; rep < 2; ++rep) {
        const int qbi = rep ? (15 - xpair) : xpair;
        const int q0 = qbi * 128;
        const int qw = q0 + w * 16;
        const bf16* Qg = g_q16 + (tok + q0) * D_MODEL + h * 64;

        // issue kv tile 0 (buffer 0 is free: previous rep ended on buffer 1)
#pragma unroll
        for (int i = 0; i < 2; ++i) {
            const int idx = tid + i * 256;
            const int r = idx >> 3, c = idx & 7;
            const uint32_t so = (r * 32 + ((c ^ (r & 7)) << 2)) << 2;
            cp16(ksb + so, Kg + (size_t)r * D_MODEL + c * 8);
            cp16(vsb + so, Vg + (size_t)r * T_ + c * 8);
        }
        CP_COMMIT;

        __syncthreads();  // protect Qs rewrite vs previous rep's readers
#pragma unroll
        for (int i = 0; i < 4; ++i) {
            const int idx = tid + i * 256;
            const int r = idx >> 3, c = idx & 7;
            const uint4 v = *(const uint4*)(Qg + (size_t)r * D_MODEL + c * 8);
            *(uint4*)&Qs[r * 32 + ((c ^ (r & 7)) << 2)] = v;
        }

        float o[8][4];
        float mi0 = -1e30f, mi1 = -1e30f, li0 = 0.f, li1 = 0.f;
#pragma unroll
        for (int nt = 0; nt < 8; nt++)
#pragma unroll
            for (int j = 0; j < 4; j++) o[nt][j] = 0.f;

        const int ntiles = 2 * qbi + 2;
        for (int kt = 0; kt < ntiles; ++kt) {
            const int k0 = kt * 64;
            CP_WAIT0;
            __syncthreads();
            if (kt + 1 < ntiles) {
                const int st = (kt + 1) & 1;
                const int kn = (kt + 1) * 64;
#pragma unroll
                for (int i = 0; i < 2; ++i) {
                    const int idx = tid + i * 256;
                    const int r = idx >> 3, c = idx & 7;
                    const uint32_t so = ((r * 32 + ((c ^ (r & 7)) << 2)) << 2) + st * 8192;
                    cp16(ksb + so, Kg + (size_t)(kn + r) * D_MODEL + c * 8);
                    cp16(vsb + so, Vg + (size_t)r * T_ + kn + c * 8);
                }
                CP_COMMIT;
            }
            if (k0 > qw + 15) continue;
            const uint32_t* Kb = Ks[kt & 1];
            const uint32_t* Vb = Vs[kt & 1];

            // S = Q K^T (warp: 16 x 64)
            float s[8][4];
#pragma unroll
            for (int nt = 0; nt < 8; nt++)
#pragma unroll
                for (int j = 0; j < 4; j++) s[nt][j] = 0.f;
#pragma unroll
            for (int kb = 0; kb < 4; ++kb) {
                const uint32_t* pq = Qs + (w * 16 + grp) * 32 + qd;
                const uint32_t x0 = ((kb * 2) ^ grp) << 2, x1 = ((kb * 2 + 1) ^ grp) << 2;
                const uint32_t a0 = pq[x0], a1 = pq[256 + x0];
                const uint32_t a2 = pq[x1], a3 = pq[256 + x1];
#pragma unroll
                for (int nt = 0; nt < 8; ++nt) {
                    const uint32_t* pkk = Kb + (nt * 8 + grp) * 32 + qd;
                    mma16(s[nt], a0, a1, a2, a3, pkk[x0], pkk[x1]);
                }
            }

            // scale to log2 domain + causal mask
            const int r0 = qw + grp, r1 = r0 + 8;
            const float SC = 0.125f * LOG2E;
#pragma unroll
            for (int nt = 0; nt < 8; nt++)
#pragma unroll
                for (int j = 0; j < 4; j++) s[nt][j] *= SC;
            if (k0 + 63 > qw) {
#pragma unroll
                for (int nt = 0; nt < 8; nt++) {
                    const int c0 = k0 + nt * 8 + 2 * qd;
                    if (c0 > r0) s[nt][0] = -1e30f;
                    if (c0 + 1 > r0) s[nt][1] = -1e30f;
                    if (c0 > r1) s[nt][2] = -1e30f;
                    if (c0 + 1 > r1) s[nt][3] = -1e30f;
                }
            }

            // online softmax (exp2 domain)
            float mx0 = -1e30f, mx1 = -1e30f;
#pragma unroll
            for (int nt = 0; nt < 8; nt++) {
                mx0 = fmaxf(mx0, fmaxf(s[nt][0], s[nt][1]));
                mx1 = fmaxf(mx1, fmaxf(s[nt][2], s[nt][3]));
            }
            mx0 = fmaxf(mx0, __shfl_xor_sync(0xffffffffu, mx0, 1));
            mx0 = fmaxf(mx0, __shfl_xor_sync(0xffffffffu, mx0, 2));
            mx1 = fmaxf(mx1, __shfl_xor_sync(0xffffffffu, mx1, 1));
            mx1 = fmaxf(mx1, __shfl_xor_sync(0xffffffffu, mx1, 2));
            const float nm0 = fmaxf(mi0, mx0), nm1 = fmaxf(mi1, mx1);
            const float al0 = exp2f(mi0 - nm0), al1 = exp2f(mi1 - nm1);
            mi0 = nm0; mi1 = nm1;

            float sum0 = 0.f, sum1 = 0.f;
#pragma unroll
            for (int nt = 0; nt < 8; nt++) {
                s[nt][0] = exp2f(s[nt][0] - nm0);
                s[nt][1] = exp2f(s[nt][1] - nm0);
                s[nt][2] = exp2f(s[nt][2] - nm1);
                s[nt][3] = exp2f(s[nt][3] - nm1);
                sum0 += s[nt][0] + s[nt][1];
                sum1 += s[nt][2] + s[nt][3];
            }
            sum0 += __shfl_xor_sync(0xffffffffu, sum0, 1);
            sum0 += __shfl_xor_sync(0xffffffffu, sum0, 2);
            sum1 += __shfl_xor_sync(0xffffffffu, sum1, 1);
            sum1 += __shfl_xor_sync(0xffffffffu, sum1, 2);
            li0 = li0 * al0 + sum0;
            li1 = li1 * al1 + sum1;

            // pack P into A-fragments (registers only)
            uint32_t pa[4][4];
#pragma unroll
            for (int ks = 0; ks < 4; ++ks) {
                pa[ks][0] = pkbf(s[2 * ks][0], s[2 * ks][1]);
                pa[ks][1] = pkbf(s[2 * ks][2], s[2 * ks][3]);
                pa[ks][2] = pkbf(s[2 * ks + 1][0], s[2 * ks + 1][1]);
                pa[ks][3] = pkbf(s[2 * ks + 1][2], s[2 * ks + 1][3]);
            }
#pragma unroll
            for (int nt = 0; nt < 8; nt++) {
                o[nt][0] *= al0; o[nt][1] *= al0;
                o[nt][2] *= al1; o[nt][3] *= al1;
            }

            // O += P @ V
#pragma unroll
            for (int ks = 0; ks < 4; ++ks) {
                const uint32_t x0 = ((ks * 2) ^ grp) << 2, x1 = ((ks * 2 + 1) ^ grp) << 2;
#pragma unroll
                for (int nt = 0; nt < 8; ++nt) {
                    const uint32_t* pv = Vb + (nt * 8 + grp) * 32 + qd;
                    mma16(o[nt], pa[ks][0], pa[ks][1], pa[ks][2], pa[ks][3], pv[x0], pv[x1]);
                }
            }
        }

        // epilogue -> attn16 [token][256]
        const float inv0 = 1.0f / li0, inv1 = 1.0f / li1;
        const int r0 = qw + grp;
#pragma unroll
        for (int nt = 0; nt < 8; ++nt) {
            const int c = h * 64 + nt * 8 + 2 * qd;
            *(uint32_t*)&g_attn16[(tok + r0) * D_MODEL + c] = pkbf(o[nt][0] * inv0, o[nt][1] * inv0);
            *(uint32_t*)&g_attn16[(tok + r0 + 8) * D_MODEL + c] = pkbf(o[nt][2] * inv1, o[nt][3] * inv1);
        }
    }
}

// -------------------- launch --------------------
extern "C" void kernel_launch(void* const* d_in, const int* in_sizes, int n_in,
                              void* d_out, int out_size) {
    const float* x          = (const float*)d_in[0];
    const float* rms_attn_w = (const float*)d_in[2];
    const float* wq         = (const float*)d_in[3];
    const float* wk         = (const float*)d_in[4];
    const float* wv         = (const float*)d_in[5];
    const float* wo         = (const float*)d_in[6];
    const float* rms_ffn_w  = (const float*)d_in[7];
    const float* wg         = (const float*)d_in[8];
    const float* wu         = (const float*)d_in[9];
    const float* wd         = (const float*)d_in[10];
    float* out = (float*)d_out;

    bf16 *w16, *attn16, *silu16;
    float* x1;
    cudaGetSymbolAddress((void**)&w16, g_w16);
    cudaGetSymbolAddress((void**)&attn16, g_attn16);
    cudaGetSymbolAddress((void**)&silu16, g_silu16);
    cudaGetSymbolAddress((void**)&x1, g_x1);

    // 1. convert weights to bf16
    cvtw_kernel<<<dim3(256, 7), 256>>>(wq, wk, wv, wo, wg, wu, wd);
    // 2. h16 = rmsnorm(x)
    rmsnorm_kernel<<<BT, 256>>>(x, rms_attn_w);
    // 3. q,k,vt
    qkv_kernel<<<dim3(BT / 64, 2, 3), 256>>>();
    // 4. attention (balanced causal pairs)
    flash_kernel<<<dim3(8, 4, B_), 256>>>();
    // 5. x1 = x + attn @ wo^T
    out_gemm_kernel<<<dim3(BT / 64, 2), 256>>>(attn16, w16 + 196608, x, x1, D_MODEL);
    // 6. h16 = rmsnorm(x1)
    rmsnorm_kernel<<<BT, 256>>>(x1, rms_ffn_w);
    // 7. silu16 = silu(h16@wg^T) * (h16@wu^T)
    gateup_kernel<<<dim3(BT / 64, D_FF / 64), 256>>>();
    // 8. out = x1 + silu16 @ wd^T
    out_gemm_kernel<<<dim3(BT / 64, 2), 256>>>(silu16, w16 + 786432, x1, out, D_FF);
}

// round 6
// speedup vs baseline: 6.9623x; 1.0143x over previous
#include <cuda_runtime.h>
#include <cuda_bf16.h>
#include <stdint.h>
#include <math.h>

#define D_MODEL 256
#define D_FF    1024
#define T_      2048
#define B_      4
#define BT      8192
#define RMS_EPS 1e-5f

typedef __nv_bfloat16 bf16;

// -------------------- scratch (no allocs allowed) --------------------
__device__ bf16  g_w16[1048576];
__device__ bf16  g_h16[BT * D_MODEL];
__device__ bf16  g_q16[BT * D_MODEL];
__device__ bf16  g_k16[BT * D_MODEL];
__device__ bf16  g_vt16[BT * D_MODEL];   // v transposed: [(b*4+h)*64+d][t]
__device__ bf16  g_attn16[BT * D_MODEL];
__device__ bf16  g_silu16[BT * D_FF];
__device__ float g_x1[BT * D_MODEL];

// -------------------- helpers --------------------
__device__ __forceinline__ uint32_t pkbf(float lo, float hi) {
    uint32_t r;
    asm("cvt.rn.bf16x2.f32 %0,%1,%2;" : "=r"(r) : "f"(hi), "f"(lo));
    return r;
}
__device__ __forceinline__ void mma16(float* d, uint32_t a0, uint32_t a1, uint32_t a2,
                                      uint32_t a3, uint32_t b0, uint32_t b1) {
    asm volatile(
        "mma.sync.aligned.m16n8k16.row.col.f32.bf16.bf16.f32 "
        "{%0,%1,%2,%3},{%4,%5,%6,%7},{%8,%9},{%0,%1,%2,%3};"
        : "+f"(d[0]), "+f"(d[1]), "+f"(d[2]), "+f"(d[3])
        : "r"(a0), "r"(a1), "r"(a2), "r"(a3), "r"(b0), "r"(b1));
}
__device__ __forceinline__ uint32_t s2u(const void* p) {
    return (uint32_t)__cvta_generic_to_shared(p);
}
__device__ __forceinline__ void cp16(uint32_t s, const void* g) {
    asm volatile("cp.async.cg.shared.global [%0],[%1],16;" :: "r"(s), "l"(g) : "memory");
}
#define CP_COMMIT asm volatile("cp.async.commit_group;" ::: "memory")
#define CP_WAIT0  asm volatile("cp.async.wait_group 0;" ::: "memory")
#define CP_WAIT1  asm volatile("cp.async.wait_group 1;" ::: "memory")

// -------------------- weight fp32 -> bf16 --------------------
__global__ void cvtw_kernel(const float* __restrict__ wq, const float* __restrict__ wk,
                            const float* __restrict__ wv, const float* __restrict__ wo,
                            const float* __restrict__ wg, const float* __restrict__ wu,
                            const float* __restrict__ wd) {
    const float* src; int n, off;
    switch (blockIdx.y) {
        case 0: src = wq; n = 65536;  off = 0;      break;
        case 1: src = wk; n = 65536;  off = 65536;  break;
        case 2: src = wv; n = 65536;  off = 131072; break;
        case 3: src = wo; n = 65536;  off = 196608; break;
        case 4: src = wg; n = 262144; off = 262144; break;
        case 5: src = wu; n = 262144; off = 524288; break;
        default: src = wd; n = 262144; off = 786432; break;
    }
    const int i = (blockIdx.x * 256 + threadIdx.x) * 4;
    if (i < n) {
        const float4 v = *(const float4*)(src + i);
        uint2 u = make_uint2(pkbf(v.x, v.y), pkbf(v.z, v.w));
        *(uint2*)&g_w16[off + i] = u;
    }
}

// -------------------- rmsnorm -> bf16 into g_h16 --------------------
__global__ void rmsnorm_kernel(const float* __restrict__ x, const float* __restrict__ w) {
    const int row = blockIdx.x;
    const int tid = threadIdx.x;
    const float v = x[(size_t)row * D_MODEL + tid];
    float ss = v * v;
#pragma unroll
    for (int m = 16; m; m >>= 1) ss += __shfl_xor_sync(0xffffffffu, ss, m);
    __shared__ float ws[8];
    __shared__ float s_tot;
    if ((tid & 31) == 0) ws[tid >> 5] = ss;
    __syncthreads();
    if (tid < 8) {
        float t = ws[tid];
        t += __shfl_xor_sync(0xffu, t, 4);
        t += __shfl_xor_sync(0xffu, t, 2);
        t += __shfl_xor_sync(0xffu, t, 1);
        if (tid == 0) s_tot = t;
    }
    __syncthreads();
    const float r = rsqrtf(s_tot * (1.0f / D_MODEL) + RMS_EPS);
    g_h16[(size_t)row * D_MODEL + tid] = __float2bfloat16(v * r * w[tid]);
}

// -------------------- bf16 GEMM core: BM=64 BN=128 BK=32, cp.async 3-stage ---
// A stage = 64x16 words = 4096B; B stage = 128x16 words = 8192B (rows 64-127 at +4096B).
__device__ __forceinline__ void gemm_core(const bf16* __restrict__ A,
                                          const bf16* __restrict__ W,
                                          int K, uint32_t* As, uint32_t* Bs,
                                          float (&acc)[2][4][4]) {
    const int tid = threadIdx.x, lane = tid & 31, w = tid >> 5;
    const int grp = lane >> 2, qd = lane & 3;
    const int bm = blockIdx.x * 64, bn = blockIdx.y * 128;
    const int wm = (w & 1) * 32, wn = (w >> 1) * 32;

#pragma unroll
    for (int mt = 0; mt < 2; mt++)
#pragma unroll
        for (int nt = 0; nt < 4; nt++)
#pragma unroll
            for (int j = 0; j < 4; j++) acc[mt][nt][j] = 0.f;

    const int ar = tid >> 2, ac = tid & 3;
    const bf16* ga  = A + (size_t)(bm + ar) * K + ac * 8;
    const bf16* gb0 = W + (size_t)(bn + ar) * K + ac * 8;
    const bf16* gb1 = gb0 + (size_t)64 * K;
    const uint32_t off = ((ar * 16 + ((ac ^ ((ar >> 1) & 3)) << 2)) << 2);
    const uint32_t sa = s2u(As) + off;
    const uint32_t sb = s2u(Bs) + off;

    const int NK = K >> 5;
    // prologue: stages 0, 1
    cp16(sa, ga); cp16(sb, gb0); cp16(sb + 4096, gb1);
    CP_COMMIT;
    if (NK > 1) {
        cp16(sa + 4096, ga + 32);
        cp16(sb + 8192, gb0 + 32);
        cp16(sb + 8192 + 4096, gb1 + 32);
    }
    CP_COMMIT;

    for (int it = 0; it < NK; ++it) {
        CP_WAIT1;
        __syncthreads();
        if (it + 2 < NK) {
            const int st = (it + 2) % 3;
            const int ko = (it + 2) << 5;
            cp16(sa + st * 4096, ga + ko);
            cp16(sb + st * 8192, gb0 + ko);
            cp16(sb + st * 8192 + 4096, gb1 + ko);
        }
        CP_COMMIT;
        const uint32_t* Ab = As + (it % 3) * 1024;
        const uint32_t* Bb = Bs + (it % 3) * 2048;
#pragma unroll
        for (int kb = 0; kb < 2; ++kb) {
            uint32_t af[2][4], bfr[4][2];
#pragma unroll
            for (int mt = 0; mt < 2; ++mt) {
                const int R = wm + mt * 16 + grp;
                const int sw = (R >> 1) & 3;
                const uint32_t* p = Ab + R * 16 + qd;
                af[mt][0] = p[((kb * 2) ^ sw) << 2];
                af[mt][1] = p[128 + (((kb * 2) ^ sw) << 2)];
                af[mt][2] = p[((kb * 2 + 1) ^ sw) << 2];
                af[mt][3] = p[128 + (((kb * 2 + 1) ^ sw) << 2)];
            }
#pragma unroll
            for (int nt = 0; nt < 4; ++nt) {
                const int R = wn + nt * 8 + grp;
                const int sw = (R >> 1) & 3;
                const uint32_t* p = Bb + R * 16 + qd;
                bfr[nt][0] = p[((kb * 2) ^ sw) << 2];
                bfr[nt][1] = p[((kb * 2 + 1) ^ sw) << 2];
            }
#pragma unroll
            for (int mt = 0; mt < 2; ++mt)
#pragma unroll
                for (int nt = 0; nt < 4; ++nt)
                    mma16(acc[mt][nt], af[mt][0], af[mt][1], af[mt][2], af[mt][3],
                          bfr[nt][0], bfr[nt][1]);
        }
    }
}

// -------------------- qkv --------------------
__global__ void __launch_bounds__(256) qkv_kernel() {
    __shared__ uint32_t As[3 * 1024];
    __shared__ uint32_t Bs[3 * 2048];
    const bf16* W = g_w16 + blockIdx.z * 65536;
    float acc[2][4][4];
    gemm_core(g_h16, W, D_MODEL, As, Bs, acc);

    const int tid = threadIdx.x, lane = tid & 31, w = tid >> 5;
    const int grp = lane >> 2, qd = lane & 3;
    const int bm = blockIdx.x * 64, bn = blockIdx.y * 128;
    const int wm = (w & 1) * 32, wn = (w >> 1) * 32;

    if (blockIdx.z < 2) {
        bf16* C = (blockIdx.z == 0) ? g_q16 : g_k16;
#pragma unroll
        for (int mt = 0; mt < 2; ++mt) {
            const int r0 = bm + wm + mt * 16 + grp;
#pragma unroll
            for (int nt = 0; nt < 4; ++nt) {
                const int c = bn + wn + nt * 8 + 2 * qd;
                *(uint32_t*)&C[(size_t)r0 * D_MODEL + c] = pkbf(acc[mt][nt][0], acc[mt][nt][1]);
                *(uint32_t*)&C[(size_t)(r0 + 8) * D_MODEL + c] = pkbf(acc[mt][nt][2], acc[mt][nt][3]);
            }
        }
    } else {
#pragma unroll
        for (int mt = 0; mt < 2; ++mt) {
            const int r0 = bm + wm + mt * 16 + grp;
            const int b0 = r0 >> 11, t0 = r0 & 2047;
            const int b1 = (r0 + 8) >> 11, t1 = (r0 + 8) & 2047;
#pragma unroll
            for (int nt = 0; nt < 4; ++nt) {
                const int c = bn + wn + nt * 8 + 2 * qd;
                const int hh = c >> 6, dd = c & 63;
                bf16* p0 = &g_vt16[((size_t)(b0 * 4 + hh) * 64 + dd) * T_ + t0];
                bf16* p1 = &g_vt16[((size_t)(b1 * 4 + hh) * 64 + dd) * T_ + t1];
                p0[0]  = __float2bfloat16(acc[mt][nt][0]);
                p0[T_] = __float2bfloat16(acc[mt][nt][1]);
                p1[0]  = __float2bfloat16(acc[mt][nt][2]);
                p1[T_] = __float2bfloat16(acc[mt][nt][3]);
            }
        }
    }
}

// -------------------- wo / down: A16 @ W^T + res -> fp32 (N=256) --------------
__global__ void __launch_bounds__(256) out_gemm_kernel(const bf16* __restrict__ A,
                                                       const bf16* __restrict__ W,
                                                       const float* __restrict__ res,
                                                       float* __restrict__ C, int K) {
    __shared__ uint32_t As[3 * 1024];
    __shared__ uint32_t Bs[3 * 2048];
    float acc[2][4][4];
    gemm_core(A, W, K, As, Bs, acc);

    const int tid = threadIdx.x, lane = tid & 31, w = tid >> 5;
    const int grp = lane >> 2, qd = lane & 3;
    const int bm = blockIdx.x * 64, bn = blockIdx.y * 128;
    const int wm = (w & 1) * 32, wn = (w >> 1) * 32;
#pragma unroll
    for (int mt = 0; mt < 2; ++mt) {
        const int r0 = bm + wm + mt * 16 + grp;
#pragma unroll
        for (int nt = 0; nt < 4; ++nt) {
            const int c = bn + wn + nt * 8 + 2 * qd;
            float2 v0 = make_float2(acc[mt][nt][0], acc[mt][nt][1]);
            float2 v1 = make_float2(acc[mt][nt][2], acc[mt][nt][3]);
            float2 rr = *(const float2*)&res[(size_t)r0 * D_MODEL + c];
            v0.x += rr.x; v0.y += rr.y;
            rr = *(const float2*)&res[(size_t)(r0 + 8) * D_MODEL + c];
            v1.x += rr.x; v1.y += rr.y;
            *(float2*)&C[(size_t)r0 * D_MODEL + c] = v0;
            *(float2*)&C[(size_t)(r0 + 8) * D_MODEL + c] = v1;
        }
    }
}

// -------------------- fused gate/up/silu (3-stage) --------------------
__global__ void __launch_bounds__(256) gateup_kernel() {
    __shared__ uint32_t As[3 * 1024];
    __shared__ uint32_t Bg[3 * 1024];
    __shared__ uint32_t Bu[3 * 1024];
    const int tid = threadIdx.x, lane = tid & 31, w = tid >> 5;
    const int grp = lane >> 2, qd = lane & 3;
    const int bm = blockIdx.x * 64, bn = blockIdx.y * 64;
    const int wm = (w & 3) * 16, wn = (w >> 2) * 32;

    float ag[4][4], au[4][4];
#pragma unroll
    for (int nt = 0; nt < 4; nt++)
#pragma unroll
        for (int j = 0; j < 4; j++) { ag[nt][j] = 0.f; au[nt][j] = 0.f; }

    const bf16* Wg = g_w16 + 262144;
    const bf16* Wu = g_w16 + 524288;
    const int ar = tid >> 2, ac = tid & 3;
    const bf16* ga = g_h16 + (size_t)(bm + ar) * D_MODEL + ac * 8;
    const bf16* gg = Wg + (size_t)(bn + ar) * D_MODEL + ac * 8;
    const bf16* gu = Wu + (size_t)(bn + ar) * D_MODEL + ac * 8;
    const uint32_t off = ((ar * 16 + ((ac ^ ((ar >> 1) & 3)) << 2)) << 2);
    const uint32_t sa = s2u(As) + off, sg = s2u(Bg) + off, su = s2u(Bu) + off;

    cp16(sa, ga); cp16(sg, gg); cp16(su, gu);
    CP_COMMIT;
    cp16(sa + 4096, ga + 32); cp16(sg + 4096, gg + 32); cp16(su + 4096, gu + 32);
    CP_COMMIT;

    const int NK = D_MODEL >> 5;  // 8
    for (int it = 0; it < NK; ++it) {
        CP_WAIT1;
        __syncthreads();
        if (it + 2 < NK) {
            const int st = (it + 2) % 3;
            const int ko = (it + 2) << 5;
            cp16(sa + st * 4096, ga + ko);
            cp16(sg + st * 4096, gg + ko);
            cp16(su + st * 4096, gu + ko);
        }
        CP_COMMIT;
        const uint32_t* Ab = As + (it % 3) * 1024;
        const uint32_t* Gb = Bg + (it % 3) * 1024;
        const uint32_t* Ub = Bu + (it % 3) * 1024;
#pragma unroll
        for (int kb = 0; kb < 2; ++kb) {
            const int R = wm + grp;
            const int sw = (R >> 1) & 3;
            const uint32_t* p = Ab + R * 16 + qd;
            const uint32_t a0 = p[((kb * 2) ^ sw) << 2];
            const uint32_t a1 = p[128 + (((kb * 2) ^ sw) << 2)];
            const uint32_t a2 = p[((kb * 2 + 1) ^ sw) << 2];
            const uint32_t a3 = p[128 + (((kb * 2 + 1) ^ sw) << 2)];
#pragma unroll
            for (int nt = 0; nt < 4; ++nt) {
                const int RB = wn + nt * 8 + grp;
                const int swb = (RB >> 1) & 3;
                const uint32_t x0 = ((kb * 2) ^ swb) << 2, x1 = ((kb * 2 + 1) ^ swb) << 2;
                const uint32_t* pg = Gb + RB * 16 + qd;
                const uint32_t* pu = Ub + RB * 16 + qd;
                mma16(ag[nt], a0, a1, a2, a3, pg[x0], pg[x1]);
                mma16(au[nt], a0, a1, a2, a3, pu[x0], pu[x1]);
            }
        }
    }

    const int r0 = bm + wm + grp;
#pragma unroll
    for (int nt = 0; nt < 4; ++nt) {
        const int c = bn + wn + nt * 8 + 2 * qd;
        float s0[4];
#pragma unroll
        for (int j = 0; j < 4; ++j) {
            const float g = ag[nt][j];
            s0[j] = (g / (1.0f + __expf(-g))) * au[nt][j];
        }
        *(uint32_t*)&g_silu16[(size_t)r0 * D_FF + c] = pkbf(s0[0], s0[1]);
        *(uint32_t*)&g_silu16[(size_t)(r0 + 8) * D_FF + c] = pkbf(s0[2], s0[3]);
    }
}

// -------------------- flash attention: 64 q-rows, 4 warps --------------------
// Grid (16,4,4): block does q-tile x (x+1 ktiles) then 31-x (32-x ktiles) = 33.
#define LOG2E 1.4426950408889634f

__global__ void __launch_bounds__(128) flash_kernel() {
    __shared__ uint32_t Qs[64 * 32];       // 8KB
    __shared__ uint32_t Ks[2][64 * 32];    // 16KB
    __shared__ uint32_t Vs[2][64 * 32];    // 16KB
    const int xpair = blockIdx.x, h = blockIdx.y, b = blockIdx.z;
    const int tid = threadIdx.x, lane = tid & 31, w = tid >> 5;
    const int grp = lane >> 2, qd = lane & 3;
    const size_t tok = (size_t)b * T_;
    const int bh = b * 4 + h;
    const bf16* Kg = g_k16 + tok * D_MODEL + h * 64;
    const bf16* Vg = g_vt16 + (size_t)bh * 64 * T_;
    const uint32_t ksb = s2u(Ks), vsb = s2u(Vs);

    for (int rep = 0; rep < 2; ++rep) {
        const int qbi = rep ? (31 - xpair) : xpair;
        const int q0 = qbi * 64;
        const int qw = q0 + w * 16;
        const bf16* Qg = g_q16 + (tok + q0) * D_MODEL + h * 64;

        __syncthreads();  // all warps done with prior rep's buffers + Qs

        // issue kv tile 0 into buffer 0
#pragma unroll
        for (int i = 0; i < 4; ++i) {
            const int idx = tid + i * 128;
            const int r = idx >> 3, c = idx & 7;
            const uint32_t so = (r * 32 + ((c ^ (r & 7)) << 2)) << 2;
            cp16(ksb + so, Kg + (size_t)r * D_MODEL + c * 8);
            cp16(vsb + so, Vg + (size_t)r * T_ + c * 8);
        }
        CP_COMMIT;

        // load Q tile
#pragma unroll
        for (int i = 0; i < 4; ++i) {
            const int idx = tid + i * 128;
            const int r = idx >> 3, c = idx & 7;
            const uint4 v = *(const uint4*)(Qg + (size_t)r * D_MODEL + c * 8);
            *(uint4*)&Qs[r * 32 + ((c ^ (r & 7)) << 2)] = v;
        }

        float o[8][4];
        float mi0 = -1e30f, mi1 = -1e30f, li0 = 0.f, li1 = 0.f;
#pragma unroll
        for (int nt = 0; nt < 8; nt++)
#pragma unroll
            for (int j = 0; j < 4; j++) o[nt][j] = 0.f;

        const int ntiles = qbi + 1;
        for (int kt = 0; kt < ntiles; ++kt) {
            const int k0 = kt * 64;
            CP_WAIT0;
            __syncthreads();
            if (kt + 1 < ntiles) {
                const int st = (kt + 1) & 1;
                const int kn = (kt + 1) * 64;
#pragma unroll
                for (int i = 0; i < 4; ++i) {
                    const int idx = tid + i * 128;
                    const int r = idx >> 3, c = idx & 7;
                    const uint32_t so = ((r * 32 + ((c ^ (r & 7)) << 2)) << 2) + st * 8192;
                    cp16(ksb + so, Kg + (size_t)(kn + r) * D_MODEL + c * 8);
                    cp16(vsb + so, Vg + (size_t)r * T_ + kn + c * 8);
                }
                CP_COMMIT;
            }
            if (k0 > qw + 15) continue;
            const uint32_t* Kb = Ks[kt & 1];
            const uint32_t* Vb = Vs[kt & 1];

            // S = Q K^T (warp: 16 x 64)
            float s[8][4];
#pragma unroll
            for (int nt = 0; nt < 8; nt++)
#pragma unroll
                for (int j = 0; j < 4; j++) s[nt][j] = 0.f;
#pragma unroll
            for (int kb = 0; kb < 4; ++kb) {
                const uint32_t* pq = Qs + (w * 16 + grp) * 32 + qd;
                const uint32_t x0 = ((kb * 2) ^ grp) << 2, x1 = ((kb * 2 + 1) ^ grp) << 2;
                const uint32_t a0 = pq[x0], a1 = pq[256 + x0];
                const uint32_t a2 = pq[x1], a3 = pq[256 + x1];
#pragma unroll
                for (int nt = 0; nt < 8; ++nt) {
                    const uint32_t* pkk = Kb + (nt * 8 + grp) * 32 + qd;
                    mma16(s[nt], a0, a1, a2, a3, pkk[x0], pkk[x1]);
                }
            }

            // scale to log2 domain + causal mask
            const int r0 = qw + grp, r1 = r0 + 8;
            const float SC = 0.125f * LOG2E;
#pragma unroll
            for (int nt = 0; nt < 8; nt++)
#pragma unroll
                for (int j = 0; j < 4; j++) s[nt][j] *= SC;
            if (k0 + 63 > qw) {
#pragma unroll
                for (int nt = 0; nt < 8; nt++) {
                    const int c0 = k0 + nt * 8 + 2 * qd;
                    if (c0 > r0) s[nt][0] = -1e30f;
                    if (c0 + 1 > r0) s[nt][1] = -1e30f;
                    if (c0 > r1) s[nt][2] = -1e30f;
                    if (c0 + 1 > r1) s[nt][3] = -1e30f;
                }
            }

            // online softmax (exp2 domain)
            float mx0 = -1e30f, mx1 = -1e30f;
#pragma unroll
            for (int nt = 0; nt < 8; nt++) {
                mx0 = fmaxf(mx0, fmaxf(s[nt][0], s[nt][1]));
                mx1 = fmaxf(mx1, fmaxf(s[nt][2], s[nt][3]));
            }
            mx0 = fmaxf(mx0, __shfl_xor_sync(0xffffffffu, mx0, 1));
            mx0 = fmaxf(mx0, __shfl_xor_sync(0xffffffffu, mx0, 2));
            mx1 = fmaxf(mx1, __shfl_xor_sync(0xffffffffu, mx1, 1));
            mx1 = fmaxf(mx1, __shfl_xor_sync(0xffffffffu, mx1, 2));
            const float nm0 = fmaxf(mi0, mx0), nm1 = fmaxf(mi1, mx1);
            const float al0 = exp2f(mi0 - nm0), al1 = exp2f(mi1 - nm1);
            mi0 = nm0; mi1 = nm1;

            float sum0 = 0.f, sum1 = 0.f;
#pragma unroll
            for (int nt = 0; nt < 8; nt++) {
                s[nt][0] = exp2f(s[nt][0] - nm0);
                s[nt][1] = exp2f(s[nt][1] - nm0);
                s[nt][2] = exp2f(s[nt][2] - nm1);
                s[nt][3] = exp2f(s[nt][3] - nm1);
                sum0 += s[nt][0] + s[nt][1];
                sum1 += s[nt][2] + s[nt][3];
            }
            sum0 += __shfl_xor_sync(0xffffffffu, sum0, 1);
            sum0 += __shfl_xor_sync(0xffffffffu, sum0, 2);
            sum1 += __shfl_xor_sync(0xffffffffu, sum1, 1);
            sum1 += __shfl_xor_sync(0xffffffffu, sum1, 2);
            li0 = li0 * al0 + sum0;
            li1 = li1 * al1 + sum1;

            // pack P into A-fragments (registers only)
            uint32_t pa[4][4];
#pragma unroll
            for (int ks = 0; ks < 4; ++ks) {
                pa[ks][0] = pkbf(s[2 * ks][0], s[2 * ks][1]);
                pa[ks][1] = pkbf(s[2 * ks][2], s[2 * ks][3]);
                pa[ks][2] = pkbf(s[2 * ks + 1][0], s[2 * ks + 1][1]);
                pa[ks][3] = pkbf(s[2 * ks + 1][2], s[2 * ks + 1][3]);
            }
#pragma unroll
            for (int nt = 0; nt < 8; nt++) {
                o[nt][0] *= al0; o[nt][1] *= al0;
                o[nt][2] *= al1; o[nt][3] *= al1;
            }

            // O += P @ V
#pragma unroll
            for (int ks = 0; ks < 4; ++ks) {
                const uint32_t x0 = ((ks * 2) ^ grp) << 2, x1 = ((ks * 2 + 1) ^ grp) << 2;
#pragma unroll
                for (int nt = 0; nt < 8; ++nt) {
                    const uint32_t* pv = Vb + (nt * 8 + grp) * 32 + qd;
                    mma16(o[nt], pa[ks][0], pa[ks][1], pa[ks][2], pa[ks][3], pv[x0], pv[x1]);
                }
            }
        }

        // epilogue -> attn16 [token][256]
        const float inv0 = 1.0f / li0, inv1 = 1.0f / li1;
        const int r0 = qw + grp;
#pragma unroll
        for (int nt = 0; nt < 8; ++nt) {
            const int c = h * 64 + nt * 8 + 2 * qd;
            *(uint32_t*)&g_attn16[(tok + r0) * D_MODEL + c] = pkbf(o[nt][0] * inv0, o[nt][1] * inv0);
            *(uint32_t*)&g_attn16[(tok + r0 + 8) * D_MODEL + c] = pkbf(o[nt][2] * inv1, o[nt][3] * inv1);
        }
    }
}

// -------------------- launch --------------------
extern "C" void kernel_launch(void* const* d_in, const int* in_sizes, int n_in,
                              void* d_out, int out_size) {
    const float* x          = (const float*)d_in[0];
    const float* rms_attn_w = (const float*)d_in[2];
    const float* wq         = (const float*)d_in[3];
    const float* wk         = (const float*)d_in[4];
    const float* wv         = (const float*)d_in[5];
    const float* wo         = (const float*)d_in[6];
    const float* rms_ffn_w  = (const float*)d_in[7];
    const float* wg         = (const float*)d_in[8];
    const float* wu         = (const float*)d_in[9];
    const float* wd         = (const float*)d_in[10];
    float* out = (float*)d_out;

    bf16 *w16, *attn16, *silu16;
    float* x1;
    cudaGetSymbolAddress((void**)&w16, g_w16);
    cudaGetSymbolAddress((void**)&attn16, g_attn16);
    cudaGetSymbolAddress((void**)&silu16, g_silu16);
    cudaGetSymbolAddress((void**)&x1, g_x1);

    // 1. convert weights to bf16
    cvtw_kernel<<<dim3(256, 7), 256>>>(wq, wk, wv, wo, wg, wu, wd);
    // 2. h16 = rmsnorm(x)
    rmsnorm_kernel<<<BT, 256>>>(x, rms_attn_w);
    // 3. q,k,vt
    qkv_kernel<<<dim3(BT / 64, 2, 3), 256>>>();
    // 4. attention (balanced causal pairs, 64-row CTAs)
    flash_kernel<<<dim3(16, 4, B_), 128>>>();
    // 5. x1 = x + attn @ wo^T
    out_gemm_kernel<<<dim3(BT / 64, 2), 256>>>(attn16, w16 + 196608, x, x1, D_MODEL);
    // 6. h16 = rmsnorm(x1)
    rmsnorm_kernel<<<BT, 256>>>(x1, rms_ffn_w);
    // 7. silu16 = silu(h16@wg^T) * (h16@wu^T)
    gateup_kernel<<<dim3(BT / 64, D_FF / 64), 256>>>();
    // 8. out = x1 + silu16 @ wd^T
    out_gemm_kernel<<<dim3(BT / 64, 2), 256>>>(silu16, w16 + 786432, x1, out, D_FF);
}

// round 7
// speedup vs baseline: 7.2817x; 1.0459x over previous
#include <cuda_runtime.h>
#include <cuda_bf16.h>
#include <stdint.h>
#include <math.h>

#define D_MODEL 256
#define D_FF    1024
#define T_      2048
#define B_      4
#define BT      8192
#define RMS_EPS 1e-5f

typedef __nv_bfloat16 bf16;

// -------------------- scratch (no allocs allowed) --------------------
__device__ bf16  g_w16[1048576];
__device__ bf16  g_h16[BT * D_MODEL];
__device__ bf16  g_q16[BT * D_MODEL];
__device__ bf16  g_k16[BT * D_MODEL];
__device__ bf16  g_vt16[BT * D_MODEL];   // v transposed: [(b*4+h)*64+d][t]
__device__ bf16  g_attn16[BT * D_MODEL];
__device__ bf16  g_silu16[BT * D_FF];
__device__ float g_x1[BT * D_MODEL];

// -------------------- helpers --------------------
__device__ __forceinline__ uint32_t pkbf(float lo, float hi) {
    uint32_t r;
    asm("cvt.rn.bf16x2.f32 %0,%1,%2;" : "=r"(r) : "f"(hi), "f"(lo));
    return r;
}
__device__ __forceinline__ void mma16(float* d, uint32_t a0, uint32_t a1, uint32_t a2,
                                      uint32_t a3, uint32_t b0, uint32_t b1) {
    asm volatile(
        "mma.sync.aligned.m16n8k16.row.col.f32.bf16.bf16.f32 "
        "{%0,%1,%2,%3},{%4,%5,%6,%7},{%8,%9},{%0,%1,%2,%3};"
        : "+f"(d[0]), "+f"(d[1]), "+f"(d[2]), "+f"(d[3])
        : "r"(a0), "r"(a1), "r"(a2), "r"(a3), "r"(b0), "r"(b1));
}
__device__ __forceinline__ void ldsm4(uint32_t& r0, uint32_t& r1, uint32_t& r2,
                                      uint32_t& r3, uint32_t addr) {
    asm volatile("ldmatrix.sync.aligned.m8n8.x4.shared.b16 {%0,%1,%2,%3},[%4];"
                 : "=r"(r0), "=r"(r1), "=r"(r2), "=r"(r3) : "r"(addr));
}
__device__ __forceinline__ uint32_t s2u(const void* p) {
    return (uint32_t)__cvta_generic_to_shared(p);
}
__device__ __forceinline__ void cp16(uint32_t s, const void* g) {
    asm volatile("cp.async.cg.shared.global [%0],[%1],16;" :: "r"(s), "l"(g) : "memory");
}
#define CP_COMMIT asm volatile("cp.async.commit_group;" ::: "memory")
#define CP_WAIT0  asm volatile("cp.async.wait_group 0;" ::: "memory")
#define CP_WAIT1  asm volatile("cp.async.wait_group 1;" ::: "memory")

// -------------------- weight fp32 -> bf16 --------------------
__global__ void cvtw_kernel(const float* __restrict__ wq, const float* __restrict__ wk,
                            const float* __restrict__ wv, const float* __restrict__ wo,
                            const float* __restrict__ wg, const float* __restrict__ wu,
                            const float* __restrict__ wd) {
    const float* src; int n, off;
    switch (blockIdx.y) {
        case 0: src = wq; n = 65536;  off = 0;      break;
        case 1: src = wk; n = 65536;  off = 65536;  break;
        case 2: src = wv; n = 65536;  off = 131072; break;
        case 3: src = wo; n = 65536;  off = 196608; break;
        case 4: src = wg; n = 262144; off = 262144; break;
        case 5: src = wu; n = 262144; off = 524288; break;
        default: src = wd; n = 262144; off = 786432; break;
    }
    const int i = (blockIdx.x * 256 + threadIdx.x) * 4;
    if (i < n) {
        const float4 v = *(const float4*)(src + i);
        uint2 u = make_uint2(pkbf(v.x, v.y), pkbf(v.z, v.w));
        *(uint2*)&g_w16[off + i] = u;
    }
}

// -------------------- rmsnorm -> bf16 into g_h16 --------------------
__global__ void rmsnorm_kernel(const float* __restrict__ x, const float* __restrict__ w) {
    const int row = blockIdx.x;
    const int tid = threadIdx.x;
    const float v = x[(size_t)row * D_MODEL + tid];
    float ss = v * v;
#pragma unroll
    for (int m = 16; m; m >>= 1) ss += __shfl_xor_sync(0xffffffffu, ss, m);
    __shared__ float ws[8];
    __shared__ float s_tot;
    if ((tid & 31) == 0) ws[tid >> 5] = ss;
    __syncthreads();
    if (tid < 8) {
        float t = ws[tid];
        t += __shfl_xor_sync(0xffu, t, 4);
        t += __shfl_xor_sync(0xffu, t, 2);
        t += __shfl_xor_sync(0xffu, t, 1);
        if (tid == 0) s_tot = t;
    }
    __syncthreads();
    const float r = rsqrtf(s_tot * (1.0f / D_MODEL) + RMS_EPS);
    g_h16[(size_t)row * D_MODEL + tid] = __float2bfloat16(v * r * w[tid]);
}

// -------------------- bf16 GEMM core: BM=64 BN=128 BK=32, LDSM fragments -----
__device__ __forceinline__ void gemm_core(const bf16* __restrict__ A,
                                          const bf16* __restrict__ W,
                                          int K, uint32_t* As, uint32_t* Bs,
                                          float (&acc)[2][4][4]) {
    const int tid = threadIdx.x, lane = tid & 31, w = tid >> 5;
    const int m4 = lane >> 3, r8 = lane & 7;
    const int bm = blockIdx.x * 64, bn = blockIdx.y * 128;
    const int wm = (w & 1) * 32, wn = (w >> 1) * 32;

#pragma unroll
    for (int mt = 0; mt < 2; mt++)
#pragma unroll
        for (int nt = 0; nt < 4; nt++)
#pragma unroll
            for (int j = 0; j < 4; j++) acc[mt][nt][j] = 0.f;

    const int ar = tid >> 2, ac = tid & 3;
    const bf16* ga  = A + (size_t)(bm + ar) * K + ac * 8;
    const bf16* gb0 = W + (size_t)(bn + ar) * K + ac * 8;
    const bf16* gb1 = gb0 + (size_t)64 * K;
    const uint32_t off = ((ar * 16 + ((ac ^ ((ar >> 1) & 3)) << 2)) << 2);
    const uint32_t sa = s2u(As) + off;
    const uint32_t sb = s2u(Bs) + off;

    // ldsm per-lane row offsets (bytes) + swizzle keys
    const int khalf = m4 >> 1;
    int rowA[2], swA[2], rowB[2], swB[2];
#pragma unroll
    for (int mt = 0; mt < 2; ++mt) {
        const int R = wm + mt * 16 + (m4 & 1) * 8 + r8;
        rowA[mt] = R * 64;
        swA[mt] = (R >> 1) & 3;
    }
#pragma unroll
    for (int g = 0; g < 2; ++g) {
        const int R = wn + (2 * g + (m4 & 1)) * 8 + r8;
        rowB[g] = R * 64;
        swB[g] = (R >> 1) & 3;
    }
    const uint32_t asb = s2u(As), bsb = s2u(Bs);

    const int NK = K >> 5;
    cp16(sa, ga); cp16(sb, gb0); cp16(sb + 4096, gb1);
    CP_COMMIT;
    if (NK > 1) {
        cp16(sa + 4096, ga + 32);
        cp16(sb + 8192, gb0 + 32);
        cp16(sb + 8192 + 4096, gb1 + 32);
    }
    CP_COMMIT;

    for (int it = 0; it < NK; ++it) {
        CP_WAIT1;
        __syncthreads();
        if (it + 2 < NK) {
            const int st = (it + 2) % 3;
            const int ko = (it + 2) << 5;
            cp16(sa + st * 4096, ga + ko);
            cp16(sb + st * 8192, gb0 + ko);
            cp16(sb + st * 8192 + 4096, gb1 + ko);
        }
        CP_COMMIT;
        const uint32_t Ab = asb + (it % 3) * 4096;
        const uint32_t Bb = bsb + (it % 3) * 8192;
#pragma unroll
        for (int kb = 0; kb < 2; ++kb) {
            uint32_t af[2][4], bfr[4][2];
#pragma unroll
            for (int mt = 0; mt < 2; ++mt)
                ldsm4(af[mt][0], af[mt][1], af[mt][2], af[mt][3],
                      Ab + rowA[mt] + (((kb * 2 + khalf) ^ swA[mt]) << 4));
#pragma unroll
            for (int g = 0; g < 2; ++g) {
                uint32_t b0, b1, b2, b3;
                ldsm4(b0, b1, b2, b3,
                      Bb + rowB[g] + (((kb * 2 + khalf) ^ swB[g]) << 4));
                bfr[2 * g][0] = b0; bfr[2 * g + 1][0] = b1;
                bfr[2 * g][1] = b2; bfr[2 * g + 1][1] = b3;
            }
#pragma unroll
            for (int mt = 0; mt < 2; ++mt)
#pragma unroll
                for (int nt = 0; nt < 4; ++nt)
                    mma16(acc[mt][nt], af[mt][0], af[mt][1], af[mt][2], af[mt][3],
                          bfr[nt][0], bfr[nt][1]);
        }
    }
}

// -------------------- qkv --------------------
__global__ void __launch_bounds__(256) qkv_kernel() {
    __shared__ uint32_t As[3 * 1024];
    __shared__ uint32_t Bs[3 * 2048];
    const bf16* W = g_w16 + blockIdx.z * 65536;
    float acc[2][4][4];
    gemm_core(g_h16, W, D_MODEL, As, Bs, acc);

    const int tid = threadIdx.x, lane = tid & 31, w = tid >> 5;
    const int grp = lane >> 2, qd = lane & 3;
    const int bm = blockIdx.x * 64, bn = blockIdx.y * 128;
    const int wm = (w & 1) * 32, wn = (w >> 1) * 32;

    if (blockIdx.z < 2) {
        bf16* C = (blockIdx.z == 0) ? g_q16 : g_k16;
#pragma unroll
        for (int mt = 0; mt < 2; ++mt) {
            const int r0 = bm + wm + mt * 16 + grp;
#pragma unroll
            for (int nt = 0; nt < 4; ++nt) {
                const int c = bn + wn + nt * 8 + 2 * qd;
                *(uint32_t*)&C[(size_t)r0 * D_MODEL + c] = pkbf(acc[mt][nt][0], acc[mt][nt][1]);
                *(uint32_t*)&C[(size_t)(r0 + 8) * D_MODEL + c] = pkbf(acc[mt][nt][2], acc[mt][nt][3]);
            }
        }
    } else {
#pragma unroll
        for (int mt = 0; mt < 2; ++mt) {
            const int r0 = bm + wm + mt * 16 + grp;
            const int b0 = r0 >> 11, t0 = r0 & 2047;
            const int b1 = (r0 + 8) >> 11, t1 = (r0 + 8) & 2047;
#pragma unroll
            for (int nt = 0; nt < 4; ++nt) {
                const int c = bn + wn + nt * 8 + 2 * qd;
                const int hh = c >> 6, dd = c & 63;
                bf16* p0 = &g_vt16[((size_t)(b0 * 4 + hh) * 64 + dd) * T_ + t0];
                bf16* p1 = &g_vt16[((size_t)(b1 * 4 + hh) * 64 + dd) * T_ + t1];
                p0[0]  = __float2bfloat16(acc[mt][nt][0]);
                p0[T_] = __float2bfloat16(acc[mt][nt][1]);
                p1[0]  = __float2bfloat16(acc[mt][nt][2]);
                p1[T_] = __float2bfloat16(acc[mt][nt][3]);
            }
        }
    }
}

// -------------------- wo / down: A16 @ W^T + res -> fp32 (N=256) --------------
__global__ void __launch_bounds__(256) out_gemm_kernel(const bf16* __restrict__ A,
                                                       const bf16* __restrict__ W,
                                                       const float* __restrict__ res,
                                                       float* __restrict__ C, int K) {
    __shared__ uint32_t As[3 * 1024];
    __shared__ uint32_t Bs[3 * 2048];
    float acc[2][4][4];
    gemm_core(A, W, K, As, Bs, acc);

    const int tid = threadIdx.x, lane = tid & 31, w = tid >> 5;
    const int grp = lane >> 2, qd = lane & 3;
    const int bm = blockIdx.x * 64, bn = blockIdx.y * 128;
    const int wm = (w & 1) * 32, wn = (w >> 1) * 32;
#pragma unroll
    for (int mt = 0; mt < 2; ++mt) {
        const int r0 = bm + wm + mt * 16 + grp;
#pragma unroll
        for (int nt = 0; nt < 4; ++nt) {
            const int c = bn + wn + nt * 8 + 2 * qd;
            float2 v0 = make_float2(acc[mt][nt][0], acc[mt][nt][1]);
            float2 v1 = make_float2(acc[mt][nt][2], acc[mt][nt][3]);
            float2 rr = *(const float2*)&res[(size_t)r0 * D_MODEL + c];
            v0.x += rr.x; v0.y += rr.y;
            rr = *(const float2*)&res[(size_t)(r0 + 8) * D_MODEL + c];
            v1.x += rr.x; v1.y += rr.y;
            *(float2*)&C[(size_t)r0 * D_MODEL + c] = v0;
            *(float2*)&C[(size_t)(r0 + 8) * D_MODEL + c] = v1;
        }
    }
}

// -------------------- fused gate/up/silu (LDSM) --------------------
__global__ void __launch_bounds__(256) gateup_kernel() {
    __shared__ uint32_t As[3 * 1024];
    __shared__ uint32_t Bg[3 * 1024];
    __shared__ uint32_t Bu[3 * 1024];
    const int tid = threadIdx.x, lane = tid & 31, w = tid >> 5;
    const int m4 = lane >> 3, r8 = lane & 7;
    const int grp = lane >> 2, qd = lane & 3;
    const int bm = blockIdx.x * 64, bn = blockIdx.y * 64;
    const int wm = (w & 3) * 16, wn = (w >> 2) * 32;

    float ag[4][4], au[4][4];
#pragma unroll
    for (int nt = 0; nt < 4; nt++)
#pragma unroll
        for (int j = 0; j < 4; j++) { ag[nt][j] = 0.f; au[nt][j] = 0.f; }

    const bf16* Wg = g_w16 + 262144;
    const bf16* Wu = g_w16 + 524288;
    const int ar = tid >> 2, ac = tid & 3;
    const bf16* ga = g_h16 + (size_t)(bm + ar) * D_MODEL + ac * 8;
    const bf16* gg = Wg + (size_t)(bn + ar) * D_MODEL + ac * 8;
    const bf16* gu = Wu + (size_t)(bn + ar) * D_MODEL + ac * 8;
    const uint32_t off = ((ar * 16 + ((ac ^ ((ar >> 1) & 3)) << 2)) << 2);
    const uint32_t sa = s2u(As) + off, sg = s2u(Bg) + off, su = s2u(Bu) + off;

    // ldsm lane offsets
    const int khalf = m4 >> 1;
    const int RA = wm + (m4 & 1) * 8 + r8;
    const int rowA = RA * 64, swA = (RA >> 1) & 3;
    int rowB[2], swB[2];
#pragma unroll
    for (int g = 0; g < 2; ++g) {
        const int R = wn + (2 * g + (m4 & 1)) * 8 + r8;
        rowB[g] = R * 64;
        swB[g] = (R >> 1) & 3;
    }
    const uint32_t asb = s2u(As), gsb = s2u(Bg), usb = s2u(Bu);

    cp16(sa, ga); cp16(sg, gg); cp16(su, gu);
    CP_COMMIT;
    cp16(sa + 4096, ga + 32); cp16(sg + 4096, gg + 32); cp16(su + 4096, gu + 32);
    CP_COMMIT;

    const int NK = D_MODEL >> 5;  // 8
    for (int it = 0; it < NK; ++it) {
        CP_WAIT1;
        __syncthreads();
        if (it + 2 < NK) {
            const int st = (it + 2) % 3;
            const int ko = (it + 2) << 5;
            cp16(sa + st * 4096, ga + ko);
            cp16(sg + st * 4096, gg + ko);
            cp16(su + st * 4096, gu + ko);
        }
        CP_COMMIT;
        const uint32_t Ab = asb + (it % 3) * 4096;
        const uint32_t Gb = gsb + (it % 3) * 4096;
        const uint32_t Ub = usb + (it % 3) * 4096;
#pragma unroll
        for (int kb = 0; kb < 2; ++kb) {
            uint32_t a0, a1, a2, a3;
            ldsm4(a0, a1, a2, a3, Ab + rowA + (((kb * 2 + khalf) ^ swA) << 4));
            uint32_t gf[4][2], uf[4][2];
#pragma unroll
            for (int g = 0; g < 2; ++g) {
                const uint32_t co = ((kb * 2 + khalf) ^ swB[g]) << 4;
                uint32_t b0, b1, b2, b3;
                ldsm4(b0, b1, b2, b3, Gb + rowB[g] + co);
                gf[2 * g][0] = b0; gf[2 * g + 1][0] = b1;
                gf[2 * g][1] = b2; gf[2 * g + 1][1] = b3;
                ldsm4(b0, b1, b2, b3, Ub + rowB[g] + co);
                uf[2 * g][0] = b0; uf[2 * g + 1][0] = b1;
                uf[2 * g][1] = b2; uf[2 * g + 1][1] = b3;
            }
#pragma unroll
            for (int nt = 0; nt < 4; ++nt) {
                mma16(ag[nt], a0, a1, a2, a3, gf[nt][0], gf[nt][1]);
                mma16(au[nt], a0, a1, a2, a3, uf[nt][0], uf[nt][1]);
            }
        }
    }

    const int r0 = bm + wm + grp;
#pragma unroll
    for (int nt = 0; nt < 4; ++nt) {
        const int c = bn + wn + nt * 8 + 2 * qd;
        float s0[4];
#pragma unroll
        for (int j = 0; j < 4; ++j) {
            const float g = ag[nt][j];
            s0[j] = (g / (1.0f + __expf(-g))) * au[nt][j];
        }
        *(uint32_t*)&g_silu16[(size_t)r0 * D_FF + c] = pkbf(s0[0], s0[1]);
        *(uint32_t*)&g_silu16[(size_t)(r0 + 8) * D_FF + c] = pkbf(s0[2], s0[3]);
    }
}

// -------------------- flash attention: 64 q-rows, 4 warps, LDSM --------------
// Grid (16,4,4): block does q-tile x (x+1 ktiles) then 31-x (32-x ktiles) = 33.
#define LOG2E 1.4426950408889634f

__global__ void __launch_bounds__(128, 3) flash_kernel() {
    __shared__ uint32_t Qs[64 * 32];       // 8KB
    __shared__ uint32_t Ks[2][64 * 32];    // 16KB
    __shared__ uint32_t Vs[2][64 * 32];    // 16KB
    const int xpair = blockIdx.x, h = blockIdx.y, b = blockIdx.z;
    const int tid = threadIdx.x, lane = tid & 31, w = tid >> 5;
    const int m4 = lane >> 3, r8 = lane & 7;
    const int grp = lane >> 2, qd = lane & 3;
    const size_t tok = (size_t)b * T_;
    const int bh = b * 4 + h;
    const bf16* Kg = g_k16 + tok * D_MODEL + h * 64;
    const bf16* Vg = g_vt16 + (size_t)bh * 64 * T_;
    const uint32_t ksb = s2u(Ks), vsb = s2u(Vs);
    const uint32_t qsb = s2u(Qs);
    const int khalf = m4 >> 1;

    // ldsm lane row offsets (row stride = 128 bytes, swizzle key = row & 7 = r8)
    const int rowQ = (w * 16 + (m4 & 1) * 8 + r8) * 128;   // within Qs
    int rowKV[4];
#pragma unroll
    for (int g = 0; g < 4; ++g) rowKV[g] = ((2 * g + (m4 & 1)) * 8 + r8) * 128;

    for (int rep = 0; rep < 2; ++rep) {
        const int qbi = rep ? (31 - xpair) : xpair;
        const int q0 = qbi * 64;
        const int qw = q0 + w * 16;
        const bf16* Qg = g_q16 + (tok + q0) * D_MODEL + h * 64;

        __syncthreads();  // all warps done with prior rep's buffers + Qs

        // issue kv tile 0 into buffer 0
#pragma unroll
        for (int i = 0; i < 4; ++i) {
            const int idx = tid + i * 128;
            const int r = idx >> 3, c = idx & 7;
            const uint32_t so = (r * 32 + ((c ^ (r & 7)) << 2)) << 2;
            cp16(ksb + so, Kg + (size_t)r * D_MODEL + c * 8);
            cp16(vsb + so, Vg + (size_t)r * T_ + c * 8);
        }
        CP_COMMIT;

        // load Q tile
#pragma unroll
        for (int i = 0; i < 4; ++i) {
            const int idx = tid + i * 128;
            const int r = idx >> 3, c = idx & 7;
            const uint4 v = *(const uint4*)(Qg + (size_t)r * D_MODEL + c * 8);
            *(uint4*)&Qs[r * 32 + ((c ^ (r & 7)) << 2)] = v;
        }

        float o[8][4];
        float mi0 = -1e30f, mi1 = -1e30f, li0 = 0.f, li1 = 0.f;
#pragma unroll
        for (int nt = 0; nt < 8; nt++)
#pragma unroll
            for (int j = 0; j < 4; j++) o[nt][j] = 0.f;

        const int ntiles = qbi + 1;
        for (int kt = 0; kt < ntiles; ++kt) {
            const int k0 = kt * 64;
            CP_WAIT0;
            __syncthreads();
            if (kt + 1 < ntiles) {
                const int st = (kt + 1) & 1;
                const int kn = (kt + 1) * 64;
#pragma unroll
                for (int i = 0; i < 4; ++i) {
                    const int idx = tid + i * 128;
                    const int r = idx >> 3, c = idx & 7;
                    const uint32_t so = ((r * 32 + ((c ^ (r & 7)) << 2)) << 2) + st * 8192;
                    cp16(ksb + so, Kg + (size_t)(kn + r) * D_MODEL + c * 8);
                    cp16(vsb + so, Vg + (size_t)r * T_ + kn + c * 8);
                }
                CP_COMMIT;
            }
            if (k0 > qw + 15) continue;
            const uint32_t Kb = ksb + (kt & 1) * 8192;
            const uint32_t Vb = vsb + (kt & 1) * 8192;

            // S = Q K^T (warp: 16 x 64), LDSM fragments
            float s[8][4];
#pragma unroll
            for (int nt = 0; nt < 8; nt++)
#pragma unroll
                for (int j = 0; j < 4; j++) s[nt][j] = 0.f;
#pragma unroll
            for (int kb = 0; kb < 4; ++kb) {
                const uint32_t co = ((kb * 2 + khalf) ^ r8) << 4;
                uint32_t a0, a1, a2, a3;
                ldsm4(a0, a1, a2, a3, qsb + rowQ + co);
                uint32_t kf[8][2];
#pragma unroll
                for (int g = 0; g < 4; ++g) {
                    uint32_t b0, b1, b2, b3;
                    ldsm4(b0, b1, b2, b3, Kb + rowKV[g] + co);
                    kf[2 * g][0] = b0; kf[2 * g + 1][0] = b1;
                    kf[2 * g][1] = b2; kf[2 * g + 1][1] = b3;
                }
#pragma unroll
                for (int nt = 0; nt < 8; ++nt)
                    mma16(s[nt], a0, a1, a2, a3, kf[nt][0], kf[nt][1]);
            }

            // scale to log2 domain + causal mask
            const int r0 = qw + grp, r1 = r0 + 8;
            const float SC = 0.125f * LOG2E;
#pragma unroll
            for (int nt = 0; nt < 8; nt++)
#pragma unroll
                for (int j = 0; j < 4; j++) s[nt][j] *= SC;
            if (k0 + 63 > qw) {
#pragma unroll
                for (int nt = 0; nt < 8; nt++) {
                    const int c0 = k0 + nt * 8 + 2 * qd;
                    if (c0 > r0) s[nt][0] = -1e30f;
                    if (c0 + 1 > r0) s[nt][1] = -1e30f;
                    if (c0 > r1) s[nt][2] = -1e30f;
                    if (c0 + 1 > r1) s[nt][3] = -1e30f;
                }
            }

            // online softmax (exp2 domain)
            float mx0 = -1e30f, mx1 = -1e30f;
#pragma unroll
            for (int nt = 0; nt < 8; nt++) {
                mx0 = fmaxf(mx0, fmaxf(s[nt][0], s[nt][1]));
                mx1 = fmaxf(mx1, fmaxf(s[nt][2], s[nt][3]));
            }
            mx0 = fmaxf(mx0, __shfl_xor_sync(0xffffffffu, mx0, 1));
            mx0 = fmaxf(mx0, __shfl_xor_sync(0xffffffffu, mx0, 2));
            mx1 = fmaxf(mx1, __shfl_xor_sync(0xffffffffu, mx1, 1));
            mx1 = fmaxf(mx1, __shfl_xor_sync(0xffffffffu, mx1, 2));
            const float nm0 = fmaxf(mi0, mx0), nm1 = fmaxf(mi1, mx1);
            const float al0 = exp2f(mi0 - nm0), al1 = exp2f(mi1 - nm1);
            mi0 = nm0; mi1 = nm1;

            float sum0 = 0.f, sum1 = 0.f;
#pragma unroll
            for (int nt = 0; nt < 8; nt++) {
                s[nt][0] = exp2f(s[nt][0] - nm0);
                s[nt][1] = exp2f(s[nt][1] - nm0);
                s[nt][2] = exp2f(s[nt][2] - nm1);
                s[nt][3] = exp2f(s[nt][3] - nm1);
                sum0 += s[nt][0] + s[nt][1];
                sum1 += s[nt][2] + s[nt][3];
            }
            sum0 += __shfl_xor_sync(0xffffffffu, sum0, 1);
            sum0 += __shfl_xor_sync(0xffffffffu, sum0, 2);
            sum1 += __shfl_xor_sync(0xffffffffu, sum1, 1);
            sum1 += __shfl_xor_sync(0xffffffffu, sum1, 2);
            li0 = li0 * al0 + sum0;
            li1 = li1 * al1 + sum1;

            // pack P into A-fragments (registers only)
            uint32_t pa[4][4];
#pragma unroll
            for (int ks = 0; ks < 4; ++ks) {
                pa[ks][0] = pkbf(s[2 * ks][0], s[2 * ks][1]);
                pa[ks][1] = pkbf(s[2 * ks][2], s[2 * ks][3]);
                pa[ks][2] = pkbf(s[2 * ks + 1][0], s[2 * ks + 1][1]);
                pa[ks][3] = pkbf(s[2 * ks + 1][2], s[2 * ks + 1][3]);
            }
#pragma unroll
            for (int nt = 0; nt < 8; nt++) {
                o[nt][0] *= al0; o[nt][1] *= al0;
                o[nt][2] *= al1; o[nt][3] *= al1;
            }

            // O += P @ V (LDSM V fragments)
#pragma unroll
            for (int ks = 0; ks < 4; ++ks) {
                const uint32_t co = ((ks * 2 + khalf) ^ r8) << 4;
                uint32_t vf[8][2];
#pragma unroll
                for (int g = 0; g < 4; ++g) {
                    uint32_t b0, b1, b2, b3;
                    ldsm4(b0, b1, b2, b3, Vb + rowKV[g] + co);
                    vf[2 * g][0] = b0; vf[2 * g + 1][0] = b1;
                    vf[2 * g][1] = b2; vf[2 * g + 1][1] = b3;
                }
#pragma unroll
                for (int nt = 0; nt < 8; ++nt)
                    mma16(o[nt], pa[ks][0], pa[ks][1], pa[ks][2], pa[ks][3],
                          vf[nt][0], vf[nt][1]);
            }
        }

        // epilogue -> attn16 [token][256]
        const float inv0 = 1.0f / li0, inv1 = 1.0f / li1;
        const int r0 = qw + grp;
#pragma unroll
        for (int nt = 0; nt < 8; ++nt) {
            const int c = h * 64 + nt * 8 + 2 * qd;
            *(uint32_t*)&g_attn16[(tok + r0) * D_MODEL + c] = pkbf(o[nt][0] * inv0, o[nt][1] * inv0);
            *(uint32_t*)&g_attn16[(tok + r0 + 8) * D_MODEL + c] = pkbf(o[nt][2] * inv1, o[nt][3] * inv1);
        }
    }
}

// -------------------- launch --------------------
extern "C" void kernel_launch(void* const* d_in, const int* in_sizes, int n_in,
                              void* d_out, int out_size) {
    const float* x          = (const float*)d_in[0];
    const float* rms_attn_w = (const float*)d_in[2];
    const float* wq         = (const float*)d_in[3];
    const float* wk         = (const float*)d_in[4];
    const float* wv         = (const float*)d_in[5];
    const float* wo         = (const float*)d_in[6];
    const float* rms_ffn_w  = (const float*)d_in[7];
    const float* wg         = (const float*)d_in[8];
    const float* wu         = (const float*)d_in[9];
    const float* wd         = (const float*)d_in[10];
    float* out = (float*)d_out;

    bf16 *w16, *attn16, *silu16;
    float* x1;
    cudaGetSymbolAddress((void**)&w16, g_w16);
    cudaGetSymbolAddress((void**)&attn16, g_attn16);
    cudaGetSymbolAddress((void**)&silu16, g_silu16);
    cudaGetSymbolAddress((void**)&x1, g_x1);

    // 1. convert weights to bf16
    cvtw_kernel<<<dim3(256, 7), 256>>>(wq, wk, wv, wo, wg, wu, wd);
    // 2. h16 = rmsnorm(x)
    rmsnorm_kernel<<<BT, 256>>>(x, rms_attn_w);
    // 3. q,k,vt
    qkv_kernel<<<dim3(BT / 64, 2, 3), 256>>>();
    // 4. attention (balanced causal pairs, 64-row CTAs)
    flash_kernel<<<dim3(16, 4, B_), 128>>>();
    // 5. x1 = x + attn @ wo^T
    out_gemm_kernel<<<dim3(BT / 64, 2), 256>>>(attn16, w16 + 196608, x, x1, D_MODEL);
    // 6. h16 = rmsnorm(x1)
    rmsnorm_kernel<<<BT, 256>>>(x1, rms_ffn_w);
    // 7. silu16 = silu(h16@wg^T) * (h16@wu^T)
    gateup_kernel<<<dim3(BT / 64, D_FF / 64), 256>>>();
    // 8. out = x1 + silu16 @ wd^T
    out_gemm_kernel<<<dim3(BT / 64, 2), 256>>>(silu16, w16 + 786432, x1, out, D_FF);
}

// round 8
// speedup vs baseline: 7.2884x; 1.0009x over previous
#include <cuda_runtime.h>
#include <cuda_bf16.h>
#include <stdint.h>
#include <math.h>

#define D_MODEL 256
#define D_FF    1024
#define T_      2048
#define B_      4
#define BT      8192
#define RMS_EPS 1e-5f

typedef __nv_bfloat16 bf16;

// -------------------- scratch (no allocs allowed) --------------------
__device__ bf16  g_w16[1048576];
__device__ bf16  g_h16[BT * D_MODEL];
__device__ bf16  g_q16[BT * D_MODEL];
__device__ bf16  g_k16[BT * D_MODEL];
__device__ bf16  g_vt16[BT * D_MODEL];   // v transposed: [(b*4+h)*64+d][t]
__device__ bf16  g_attn16[BT * D_MODEL];
__device__ bf16  g_silu16[BT * D_FF];
__device__ float g_x1[BT * D_MODEL];

// -------------------- helpers --------------------
__device__ __forceinline__ uint32_t pkbf(float lo, float hi) {
    uint32_t r;
    asm("cvt.rn.bf16x2.f32 %0,%1,%2;" : "=r"(r) : "f"(hi), "f"(lo));
    return r;
}
__device__ __forceinline__ void mma16(float* d, uint32_t a0, uint32_t a1, uint32_t a2,
                                      uint32_t a3, uint32_t b0, uint32_t b1) {
    asm volatile(
        "mma.sync.aligned.m16n8k16.row.col.f32.bf16.bf16.f32 "
        "{%0,%1,%2,%3},{%4,%5,%6,%7},{%8,%9},{%0,%1,%2,%3};"
        : "+f"(d[0]), "+f"(d[1]), "+f"(d[2]), "+f"(d[3])
        : "r"(a0), "r"(a1), "r"(a2), "r"(a3), "r"(b0), "r"(b1));
}
__device__ __forceinline__ void ldsm4(uint32_t& r0, uint32_t& r1, uint32_t& r2,
                                      uint32_t& r3, uint32_t addr) {
    asm volatile("ldmatrix.sync.aligned.m8n8.x4.shared.b16 {%0,%1,%2,%3},[%4];"
                 : "=r"(r0), "=r"(r1), "=r"(r2), "=r"(r3) : "r"(addr));
}
__device__ __forceinline__ uint32_t s2u(const void* p) {
    return (uint32_t)__cvta_generic_to_shared(p);
}
__device__ __forceinline__ void cp16(uint32_t s, const void* g) {
    asm volatile("cp.async.cg.shared.global [%0],[%1],16;" :: "r"(s), "l"(g) : "memory");
}
#define CP_COMMIT asm volatile("cp.async.commit_group;" ::: "memory")
#define CP_WAIT0  asm volatile("cp.async.wait_group 0;" ::: "memory")
#define CP_WAIT1  asm volatile("cp.async.wait_group 1;" ::: "memory")

// -------------------- weight fp32 -> bf16 --------------------
__global__ void cvtw_kernel(const float* __restrict__ wq, const float* __restrict__ wk,
                            const float* __restrict__ wv, const float* __restrict__ wo,
                            const float* __restrict__ wg, const float* __restrict__ wu,
                            const float* __restrict__ wd) {
    const float* src; int n, off;
    switch (blockIdx.y) {
        case 0: src = wq; n = 65536;  off = 0;      break;
        case 1: src = wk; n = 65536;  off = 65536;  break;
        case 2: src = wv; n = 65536;  off = 131072; break;
        case 3: src = wo; n = 65536;  off = 196608; break;
        case 4: src = wg; n = 262144; off = 262144; break;
        case 5: src = wu; n = 262144; off = 524288; break;
        default: src = wd; n = 262144; off = 786432; break;
    }
    const int i = (blockIdx.x * 256 + threadIdx.x) * 4;
    if (i < n) {
        const float4 v = *(const float4*)(src + i);
        uint2 u = make_uint2(pkbf(v.x, v.y), pkbf(v.z, v.w));
        *(uint2*)&g_w16[off + i] = u;
    }
}

// -------------------- rmsnorm -> bf16 into g_h16 --------------------
__global__ void rmsnorm_kernel(const float* __restrict__ x, const float* __restrict__ w) {
    const int row = blockIdx.x;
    const int tid = threadIdx.x;
    const float v = x[(size_t)row * D_MODEL + tid];
    float ss = v * v;
#pragma unroll
    for (int m = 16; m; m >>= 1) ss += __shfl_xor_sync(0xffffffffu, ss, m);
    __shared__ float ws[8];
    __shared__ float s_tot;
    if ((tid & 31) == 0) ws[tid >> 5] = ss;
    __syncthreads();
    if (tid < 8) {
        float t = ws[tid];
        t += __shfl_xor_sync(0xffu, t, 4);
        t += __shfl_xor_sync(0xffu, t, 2);
        t += __shfl_xor_sync(0xffu, t, 1);
        if (tid == 0) s_tot = t;
    }
    __syncthreads();
    const float r = rsqrtf(s_tot * (1.0f / D_MODEL) + RMS_EPS);
    g_h16[(size_t)row * D_MODEL + tid] = __float2bfloat16(v * r * w[tid]);
}

// -------------------- bf16 GEMM core: BM=64 BN=128 BK=32, LDSM fragments -----
__device__ __forceinline__ void gemm_core(const bf16* __restrict__ A,
                                          const bf16* __restrict__ W,
                                          int K, uint32_t* As, uint32_t* Bs,
                                          float (&acc)[2][4][4]) {
    const int tid = threadIdx.x, lane = tid & 31, w = tid >> 5;
    const int m4 = lane >> 3, r8 = lane & 7;
    const int bm = blockIdx.x * 64, bn = blockIdx.y * 128;
    const int wm = (w & 1) * 32, wn = (w >> 1) * 32;

#pragma unroll
    for (int mt = 0; mt < 2; mt++)
#pragma unroll
        for (int nt = 0; nt < 4; nt++)
#pragma unroll
            for (int j = 0; j < 4; j++) acc[mt][nt][j] = 0.f;

    const int ar = tid >> 2, ac = tid & 3;
    const bf16* ga  = A + (size_t)(bm + ar) * K + ac * 8;
    const bf16* gb0 = W + (size_t)(bn + ar) * K + ac * 8;
    const bf16* gb1 = gb0 + (size_t)64 * K;
    const uint32_t off = ((ar * 16 + ((ac ^ ((ar >> 1) & 3)) << 2)) << 2);
    const uint32_t sa = s2u(As) + off;
    const uint32_t sb = s2u(Bs) + off;

    // ldsm per-lane row offsets (bytes) + swizzle keys
    const int khalf = m4 >> 1;
    int rowA[2], swA[2], rowB[2], swB[2];
#pragma unroll
    for (int mt = 0; mt < 2; ++mt) {
        const int R = wm + mt * 16 + (m4 & 1) * 8 + r8;
        rowA[mt] = R * 64;
        swA[mt] = (R >> 1) & 3;
    }
#pragma unroll
    for (int g = 0; g < 2; ++g) {
        const int R = wn + (2 * g + (m4 & 1)) * 8 + r8;
        rowB[g] = R * 64;
        swB[g] = (R >> 1) & 3;
    }
    const uint32_t asb = s2u(As), bsb = s2u(Bs);

    const int NK = K >> 5;
    cp16(sa, ga); cp16(sb, gb0); cp16(sb + 4096, gb1);
    CP_COMMIT;
    if (NK > 1) {
        cp16(sa + 4096, ga + 32);
        cp16(sb + 8192, gb0 + 32);
        cp16(sb + 8192 + 4096, gb1 + 32);
    }
    CP_COMMIT;

    for (int it = 0; it < NK; ++it) {
        CP_WAIT1;
        __syncthreads();
        if (it + 2 < NK) {
            const int st = (it + 2) % 3;
            const int ko = (it + 2) << 5;
            cp16(sa + st * 4096, ga + ko);
            cp16(sb + st * 8192, gb0 + ko);
            cp16(sb + st * 8192 + 4096, gb1 + ko);
        }
        CP_COMMIT;
        const uint32_t Ab = asb + (it % 3) * 4096;
        const uint32_t Bb = bsb + (it % 3) * 8192;
#pragma unroll
        for (int kb = 0; kb < 2; ++kb) {
            uint32_t af[2][4], bfr[4][2];
#pragma unroll
            for (int mt = 0; mt < 2; ++mt)
                ldsm4(af[mt][0], af[mt][1], af[mt][2], af[mt][3],
                      Ab + rowA[mt] + (((kb * 2 + khalf) ^ swA[mt]) << 4));
#pragma unroll
            for (int g = 0; g < 2; ++g) {
                uint32_t b0, b1, b2, b3;
                ldsm4(b0, b1, b2, b3,
                      Bb + rowB[g] + (((kb * 2 + khalf) ^ swB[g]) << 4));
                bfr[2 * g][0] = b0; bfr[2 * g + 1][0] = b1;
                bfr[2 * g][1] = b2; bfr[2 * g + 1][1] = b3;
            }
#pragma unroll
            for (int mt = 0; mt < 2; ++mt)
#pragma unroll
                for (int nt = 0; nt < 4; ++nt)
                    mma16(acc[mt][nt], af[mt][0], af[mt][1], af[mt][2], af[mt][3],
                          bfr[nt][0], bfr[nt][1]);
        }
    }
}

// -------------------- qkv --------------------
__global__ void __launch_bounds__(256) qkv_kernel() {
    __shared__ uint32_t As[3 * 1024];
    __shared__ uint32_t Bs[3 * 2048];
    const bf16* W = g_w16 + blockIdx.z * 65536;
    float acc[2][4][4];
    gemm_core(g_h16, W, D_MODEL, As, Bs, acc);

    const int tid = threadIdx.x, lane = tid & 31, w = tid >> 5;
    const int grp = lane >> 2, qd = lane & 3;
    const int bm = blockIdx.x * 64, bn = blockIdx.y * 128;
    const int wm = (w & 1) * 32, wn = (w >> 1) * 32;

    if (blockIdx.z < 2) {
        bf16* C = (blockIdx.z == 0) ? g_q16 : g_k16;
#pragma unroll
        for (int mt = 0; mt < 2; ++mt) {
            const int r0 = bm + wm + mt * 16 + grp;
#pragma unroll
            for (int nt = 0; nt < 4; ++nt) {
                const int c = bn + wn + nt * 8 + 2 * qd;
                *(uint32_t*)&C[(size_t)r0 * D_MODEL + c] = pkbf(acc[mt][nt][0], acc[mt][nt][1]);
                *(uint32_t*)&C[(size_t)(r0 + 8) * D_MODEL + c] = pkbf(acc[mt][nt][2], acc[mt][nt][3]);
            }
        }
    } else {
#pragma unroll
        for (int mt = 0; mt < 2; ++mt) {
            const int r0 = bm + wm + mt * 16 + grp;
            const int b0 = r0 >> 11, t0 = r0 & 2047;
            const int b1 = (r0 + 8) >> 11, t1 = (r0 + 8) & 2047;
#pragma unroll
            for (int nt = 0; nt < 4; ++nt) {
                const int c = bn + wn + nt * 8 + 2 * qd;
                const int hh = c >> 6, dd = c & 63;
                bf16* p0 = &g_vt16[((size_t)(b0 * 4 + hh) * 64 + dd) * T_ + t0];
                bf16* p1 = &g_vt16[((size_t)(b1 * 4 + hh) * 64 + dd) * T_ + t1];
                p0[0]  = __float2bfloat16(acc[mt][nt][0]);
                p0[T_] = __float2bfloat16(acc[mt][nt][1]);
                p1[0]  = __float2bfloat16(acc[mt][nt][2]);
                p1[T_] = __float2bfloat16(acc[mt][nt][3]);
            }
        }
    }
}

// -------------------- wo / down: A16 @ W^T + res -> fp32 (N=256) --------------
__global__ void __launch_bounds__(256) out_gemm_kernel(const bf16* __restrict__ A,
                                                       const bf16* __restrict__ W,
                                                       const float* __restrict__ res,
                                                       float* __restrict__ C, int K) {
    __shared__ uint32_t As[3 * 1024];
    __shared__ uint32_t Bs[3 * 2048];
    float acc[2][4][4];
    gemm_core(A, W, K, As, Bs, acc);

    const int tid = threadIdx.x, lane = tid & 31, w = tid >> 5;
    const int grp = lane >> 2, qd = lane & 3;
    const int bm = blockIdx.x * 64, bn = blockIdx.y * 128;
    const int wm = (w & 1) * 32, wn = (w >> 1) * 32;
#pragma unroll
    for (int mt = 0; mt < 2; ++mt) {
        const int r0 = bm + wm + mt * 16 + grp;
#pragma unroll
        for (int nt = 0; nt < 4; ++nt) {
            const int c = bn + wn + nt * 8 + 2 * qd;
            float2 v0 = make_float2(acc[mt][nt][0], acc[mt][nt][1]);
            float2 v1 = make_float2(acc[mt][nt][2], acc[mt][nt][3]);
            float2 rr = *(const float2*)&res[(size_t)r0 * D_MODEL + c];
            v0.x += rr.x; v0.y += rr.y;
            rr = *(const float2*)&res[(size_t)(r0 + 8) * D_MODEL + c];
            v1.x += rr.x; v1.y += rr.y;
            *(float2*)&C[(size_t)r0 * D_MODEL + c] = v0;
            *(float2*)&C[(size_t)(r0 + 8) * D_MODEL + c] = v1;
        }
    }
}

// -------------------- fused gate/up/silu (LDSM) --------------------
__global__ void __launch_bounds__(256) gateup_kernel() {
    __shared__ uint32_t As[3 * 1024];
    __shared__ uint32_t Bg[3 * 1024];
    __shared__ uint32_t Bu[3 * 1024];
    const int tid = threadIdx.x, lane = tid & 31, w = tid >> 5;
    const int m4 = lane >> 3, r8 = lane & 7;
    const int grp = lane >> 2, qd = lane & 3;
    const int bm = blockIdx.x * 64, bn = blockIdx.y * 64;
    const int wm = (w & 3) * 16, wn = (w >> 2) * 32;

    float ag[4][4], au[4][4];
#pragma unroll
    for (int nt = 0; nt < 4; nt++)
#pragma unroll
        for (int j = 0; j < 4; j++) { ag[nt][j] = 0.f; au[nt][j] = 0.f; }

    const bf16* Wg = g_w16 + 262144;
    const bf16* Wu = g_w16 + 524288;
    const int ar = tid >> 2, ac = tid & 3;
    const bf16* ga = g_h16 + (size_t)(bm + ar) * D_MODEL + ac * 8;
    const bf16* gg = Wg + (size_t)(bn + ar) * D_MODEL + ac * 8;
    const bf16* gu = Wu + (size_t)(bn + ar) * D_MODEL + ac * 8;
    const uint32_t off = ((ar * 16 + ((ac ^ ((ar >> 1) & 3)) << 2)) << 2);
    const uint32_t sa = s2u(As) + off, sg = s2u(Bg) + off, su = s2u(Bu) + off;

    // ldsm lane offsets
    const int khalf = m4 >> 1;
    const int RA = wm + (m4 & 1) * 8 + r8;
    const int rowA = RA * 64, swA = (RA >> 1) & 3;
    int rowB[2], swB[2];
#pragma unroll
    for (int g = 0; g < 2; ++g) {
        const int R = wn + (2 * g + (m4 & 1)) * 8 + r8;
        rowB[g] = R * 64;
        swB[g] = (R >> 1) & 3;
    }
    const uint32_t asb = s2u(As), gsb = s2u(Bg), usb = s2u(Bu);

    cp16(sa, ga); cp16(sg, gg); cp16(su, gu);
    CP_COMMIT;
    cp16(sa + 4096, ga + 32); cp16(sg + 4096, gg + 32); cp16(su + 4096, gu + 32);
    CP_COMMIT;

    const int NK = D_MODEL >> 5;  // 8
    for (int it = 0; it < NK; ++it) {
        CP_WAIT1;
        __syncthreads();
        if (it + 2 < NK) {
            const int st = (it + 2) % 3;
            const int ko = (it + 2) << 5;
            cp16(sa + st * 4096, ga + ko);
            cp16(sg + st * 4096, gg + ko);
            cp16(su + st * 4096, gu + ko);
        }
        CP_COMMIT;
        const uint32_t Ab = asb + (it % 3) * 4096;
        const uint32_t Gb = gsb + (it % 3) * 4096;
        const uint32_t Ub = usb + (it % 3) * 4096;
#pragma unroll
        for (int kb = 0; kb < 2; ++kb) {
            uint32_t a0, a1, a2, a3;
            ldsm4(a0, a1, a2, a3, Ab + rowA + (((kb * 2 + khalf) ^ swA) << 4));
            uint32_t gf[4][2], uf[4][2];
#pragma unroll
            for (int g = 0; g < 2; ++g) {
                const uint32_t co = ((kb * 2 + khalf) ^ swB[g]) << 4;
                uint32_t b0, b1, b2, b3;
                ldsm4(b0, b1, b2, b3, Gb + rowB[g] + co);
                gf[2 * g][0] = b0; gf[2 * g + 1][0] = b1;
                gf[2 * g][1] = b2; gf[2 * g + 1][1] = b3;
                ldsm4(b0, b1, b2, b3, Ub + rowB[g] + co);
                uf[2 * g][0] = b0; uf[2 * g + 1][0] = b1;
                uf[2 * g][1] = b2; uf[2 * g + 1][1] = b3;
            }
#pragma unroll
            for (int nt = 0; nt < 4; ++nt) {
                mma16(ag[nt], a0, a1, a2, a3, gf[nt][0], gf[nt][1]);
                mma16(au[nt], a0, a1, a2, a3, uf[nt][0], uf[nt][1]);
            }
        }
    }

    const int r0 = bm + wm + grp;
#pragma unroll
    for (int nt = 0; nt < 4; ++nt) {
        const int c = bn + wn + nt * 8 + 2 * qd;
        float s0[4];
#pragma unroll
        for (int j = 0; j < 4; ++j) {
            const float g = ag[nt][j];
            s0[j] = (g / (1.0f + __expf(-g))) * au[nt][j];
        }
        *(uint32_t*)&g_silu16[(size_t)r0 * D_FF + c] = pkbf(s0[0], s0[1]);
        *(uint32_t*)&g_silu16[(size_t)(r0 + 8) * D_FF + c] = pkbf(s0[2], s0[3]);
    }
}

// -------------------- flash attention: 64 q-rows, 4 warps, LDSM --------------
// Grid (16,4,4): block does q-tile x (x+1 ktiles) then 31-x (32-x ktiles) = 33.
#define LOG2E 1.4426950408889634f

__global__ void __launch_bounds__(128, 3) flash_kernel() {
    __shared__ uint32_t Qs[64 * 32];       // 8KB
    __shared__ uint32_t Ks[2][64 * 32];    // 16KB
    __shared__ uint32_t Vs[2][64 * 32];    // 16KB
    const int xpair = blockIdx.x, h = blockIdx.y, b = blockIdx.z;
    const int tid = threadIdx.x, lane = tid & 31, w = tid >> 5;
    const int m4 = lane >> 3, r8 = lane & 7;
    const int grp = lane >> 2, qd = lane & 3;
    const size_t tok = (size_t)b * T_;
    const int bh = b * 4 + h;
    const bf16* Kg = g_k16 + tok * D_MODEL + h * 64;
    const bf16* Vg = g_vt16 + (size_t)bh * 64 * T_;
    const uint32_t ksb = s2u(Ks), vsb = s2u(Vs);
    const uint32_t qsb = s2u(Qs);
    const int khalf = m4 >> 1;

    // ldsm lane row offsets (row stride = 128 bytes, swizzle key = row & 7 = r8)
    const int rowQ = (w * 16 + (m4 & 1) * 8 + r8) * 128;   // within Qs
    int rowKV[4];
#pragma unroll
    for (int g = 0; g < 4; ++g) rowKV[g] = ((2 * g + (m4 & 1)) * 8 + r8) * 128;

    for (int rep = 0; rep < 2; ++rep) {
        const int qbi = rep ? (31 - xpair) : xpair;
        const int q0 = qbi * 64;
        const int qw = q0 + w * 16;
        const bf16* Qg = g_q16 + (tok + q0) * D_MODEL + h * 64;

        __syncthreads();  // all warps done with prior rep's buffers + Qs

        // issue kv tile 0 into buffer 0
#pragma unroll
        for (int i = 0; i < 4; ++i) {
            const int idx = tid + i * 128;
            const int r = idx >> 3, c = idx & 7;
            const uint32_t so = (r * 32 + ((c ^ (r & 7)) << 2)) << 2;
            cp16(ksb + so, Kg + (size_t)r * D_MODEL + c * 8);
            cp16(vsb + so, Vg + (size_t)r * T_ + c * 8);
        }
        CP_COMMIT;

        // load Q tile
#pragma unroll
        for (int i = 0; i < 4; ++i) {
            const int idx = tid + i * 128;
            const int r = idx >> 3, c = idx & 7;
            const uint4 v = *(const uint4*)(Qg + (size_t)r * D_MODEL + c * 8);
            *(uint4*)&Qs[r * 32 + ((c ^ (r & 7)) << 2)] = v;
        }

        float o[8][4];
        float mi0 = -1e30f, mi1 = -1e30f, li0 = 0.f, li1 = 0.f;
#pragma unroll
        for (int nt = 0; nt < 8; nt++)
#pragma unroll
            for (int j = 0; j < 4; j++) o[nt][j] = 0.f;

        const int ntiles = qbi + 1;
        for (int kt = 0; kt < ntiles; ++kt) {
            const int k0 = kt * 64;
            CP_WAIT0;
            __syncthreads();
            if (kt + 1 < ntiles) {
                const int st = (kt + 1) & 1;
                const int kn = (kt + 1) * 64;
#pragma unroll
                for (int i = 0; i < 4; ++i) {
                    const int idx = tid + i * 128;
                    const int r = idx >> 3, c = idx & 7;
                    const uint32_t so = ((r * 32 + ((c ^ (r & 7)) << 2)) << 2) + st * 8192;
                    cp16(ksb + so, Kg + (size_t)(kn + r) * D_MODEL + c * 8);
                    cp16(vsb + so, Vg + (size_t)r * T_ + kn + c * 8);
                }
                CP_COMMIT;
            }
            if (k0 > qw + 15) continue;
            const uint32_t Kb = ksb + (kt & 1) * 8192;
            const uint32_t Vb = vsb + (kt & 1) * 8192;

            // S = Q K^T (warp: 16 x 64), LDSM fragments
            float s[8][4];
#pragma unroll
            for (int nt = 0; nt < 8; nt++)
#pragma unroll
                for (int j = 0; j < 4; j++) s[nt][j] = 0.f;
#pragma unroll
            for (int kb = 0; kb < 4; ++kb) {
                const uint32_t co = ((kb * 2 + khalf) ^ r8) << 4;
                uint32_t a0, a1, a2, a3;
                ldsm4(a0, a1, a2, a3, qsb + rowQ + co);
                uint32_t kf[8][2];
#pragma unroll
                for (int g = 0; g < 4; ++g) {
                    uint32_t b0, b1, b2, b3;
                    ldsm4(b0, b1, b2, b3, Kb + rowKV[g] + co);
                    kf[2 * g][0] = b0; kf[2 * g + 1][0] = b1;
                    kf[2 * g][1] = b2; kf[2 * g + 1][1] = b3;
                }
#pragma unroll
                for (int nt = 0; nt < 8; ++nt)
                    mma16(s[nt], a0, a1, a2, a3, kf[nt][0], kf[nt][1]);
            }

            // scale to log2 domain + causal mask
            const int r0 = qw + grp, r1 = r0 + 8;
            const float SC = 0.125f * LOG2E;
#pragma unroll
            for (int nt = 0; nt < 8; nt++)
#pragma unroll
                for (int j = 0; j < 4; j++) s[nt][j] *= SC;
            if (k0 + 63 > qw) {
#pragma unroll
                for (int nt = 0; nt < 8; nt++) {
                    const int c0 = k0 + nt * 8 + 2 * qd;
                    if (c0 > r0) s[nt][0] = -1e30f;
                    if (c0 + 1 > r0) s[nt][1] = -1e30f;
                    if (c0 > r1) s[nt][2] = -1e30f;
                    if (c0 + 1 > r1) s[nt][3] = -1e30f;
                }
            }

            // online softmax (exp2 domain)
            float mx0 = -1e30f, mx1 = -1e30f;
#pragma unroll
            for (int nt = 0; nt < 8; nt++) {
                mx0 = fmaxf(mx0, fmaxf(s[nt][0], s[nt][1]));
                mx1 = fmaxf(mx1, fmaxf(s[nt][2], s[nt][3]));
            }
            mx0 = fmaxf(mx0, __shfl_xor_sync(0xffffffffu, mx0, 1));
            mx0 = fmaxf(mx0, __shfl_xor_sync(0xffffffffu, mx0, 2));
            mx1 = fmaxf(mx1, __shfl_xor_sync(0xffffffffu, mx1, 1));
            mx1 = fmaxf(mx1, __shfl_xor_sync(0xffffffffu, mx1, 2));
            const float nm0 = fmaxf(mi0, mx0), nm1 = fmaxf(mi1, mx1);
            const float al0 = exp2f(mi0 - nm0), al1 = exp2f(mi1 - nm1);
            mi0 = nm0; mi1 = nm1;

            float sum0 = 0.f, sum1 = 0.f;
#pragma unroll
            for (int nt = 0; nt < 8; nt++) {
                s[nt][0] = exp2f(s[nt][0] - nm0);
                s[nt][1] = exp2f(s[nt][1] - nm0);
                s[nt][2] = exp2f(s[nt][2] - nm1);
                s[nt][3] = exp2f(s[nt][3] - nm1);
                sum0 += s[nt][0] + s[nt][1];
                sum1 += s[nt][2] + s[nt][3];
            }
            sum0 += __shfl_xor_sync(0xffffffffu, sum0, 1);
            sum0 += __shfl_xor_sync(0xffffffffu, sum0, 2);
            sum1 += __shfl_xor_sync(0xffffffffu, sum1, 1);
            sum1 += __shfl_xor_sync(0xffffffffu, sum1, 2);
            li0 = li0 * al0 + sum0;
            li1 = li1 * al1 + sum1;

            // pack P into A-fragments (registers only)
            uint32_t pa[4][4];
#pragma unroll
            for (int ks = 0; ks < 4; ++ks) {
                pa[ks][0] = pkbf(s[2 * ks][0], s[2 * ks][1]);
                pa[ks][1] = pkbf(s[2 * ks][2], s[2 * ks][3]);
                pa[ks][2] = pkbf(s[2 * ks + 1][0], s[2 * ks + 1][1]);
                pa[ks][3] = pkbf(s[2 * ks + 1][2], s[2 * ks + 1][3]);
            }
#pragma unroll
            for (int nt = 0; nt < 8; nt++) {
                o[nt][0] *= al0; o[nt][1] *= al0;
                o[nt][2] *= al1; o[nt][3] *= al1;
            }

            // O += P @ V (LDSM V fragments)
#pragma unroll
            for (int ks = 0; ks < 4; ++ks) {
                const uint32_t co = ((ks * 2 + khalf) ^ r8) << 4;
                uint32_t vf[8][2];
#pragma unroll
                for (int g = 0; g < 4; ++g) {
                    uint32_t b0, b1, b2, b3;
                    ldsm4(b0, b1, b2, b3, Vb + rowKV[g] + co);
                    vf[2 * g][0] = b0; vf[2 * g + 1][0] = b1;
                    vf[2 * g][1] = b2; vf[2 * g + 1][1] = b3;
                }
#pragma unroll
                for (int nt = 0; nt < 8; ++nt)
                    mma16(o[nt], pa[ks][0], pa[ks][1], pa[ks][2], pa[ks][3],
                          vf[nt][0], vf[nt][1]);
            }
        }

        // epilogue -> attn16 [token][256]
        const float inv0 = 1.0f / li0, inv1 = 1.0f / li1;
        const int r0 = qw + grp;
#pragma unroll
        for (int nt = 0; nt < 8; ++nt) {
            const int c = h * 64 + nt * 8 + 2 * qd;
            *(uint32_t*)&g_attn16[(tok + r0) * D_MODEL + c] = pkbf(o[nt][0] * inv0, o[nt][1] * inv0);
            *(uint32_t*)&g_attn16[(tok + r0 + 8) * D_MODEL + c] = pkbf(o[nt][2] * inv1, o[nt][3] * inv1);
        }
    }
}

// -------------------- launch --------------------
extern "C" void kernel_launch(void* const* d_in, const int* in_sizes, int n_in,
                              void* d_out, int out_size) {
    const float* x          = (const float*)d_in[0];
    const float* rms_attn_w = (const float*)d_in[2];
    const float* wq         = (const float*)d_in[3];
    const float* wk         = (const float*)d_in[4];
    const float* wv         = (const float*)d_in[5];
    const float* wo         = (const float*)d_in[6];
    const float* rms_ffn_w  = (const float*)d_in[7];
    const float* wg         = (const float*)d_in[8];
    const float* wu         = (const float*)d_in[9];
    const float* wd         = (const float*)d_in[10];
    float* out = (float*)d_out;

    bf16 *w16, *attn16, *silu16;
    float* x1;
    cudaGetSymbolAddress((void**)&w16, g_w16);
    cudaGetSymbolAddress((void**)&attn16, g_attn16);
    cudaGetSymbolAddress((void**)&silu16, g_silu16);
    cudaGetSymbolAddress((void**)&x1, g_x1);

    // 1. convert weights to bf16
    cvtw_kernel<<<dim3(256, 7), 256>>>(wq, wk, wv, wo, wg, wu, wd);
    // 2. h16 = rmsnorm(x)
    rmsnorm_kernel<<<BT, 256>>>(x, rms_attn_w);
    // 3. q,k,vt
    qkv_kernel<<<dim3(BT / 64, 2, 3), 256>>>();
    // 4. attention (balanced causal pairs, 64-row CTAs)
    flash_kernel<<<dim3(16, 4, B_), 128>>>();
    // 5. x1 = x + attn @ wo^T
    out_gemm_kernel<<<dim3(BT / 64, 2), 256>>>(attn16, w16 + 196608, x, x1, D_MODEL);
    // 6. h16 = rmsnorm(x1)
    rmsnorm_kernel<<<BT, 256>>>(x1, rms_ffn_w);
    // 7. silu16 = silu(h16@wg^T) * (h16@wu^T)
    gateup_kernel<<<dim3(BT / 64, D_FF / 64), 256>>>();
    // 8. out = x1 + silu16 @ wd^T
    out_gemm_kernel<<<dim3(BT / 64, 2), 256>>>(silu16, w16 + 786432, x1, out, D_FF);
}